// round 2
// baseline (speedup 1.0000x reference)
#include <cuda_runtime.h>
#include <math.h>

#define N_HEAD 16
#define N_EMBD 1024
#define HD     64
#define B_     4
#define T_     2048
#define M_TOK  (B_ * T_)
#define C3     (3 * N_EMBD)

// Scratch (device globals — no allocation allowed in kernel_launch)
__device__ float g_qkv[(size_t)M_TOK * C3];     // [B*T, 3C]
__device__ float g_att[(size_t)M_TOK * N_EMBD]; // [B*T, C] attention output

// ---------------------------------------------------------------------------
// GEMM: C[M,N] = A[M,K] @ W[N,K]^T + bias[N]
// 128x128 tile, BK=16, 256 threads, 8x8 per thread, fp32.
// ---------------------------------------------------------------------------
#define BM  128
#define BN  128
#define BKT 16

__global__ __launch_bounds__(256) void gemm_abt(
    const float* __restrict__ A, const float* __restrict__ W,
    const float* __restrict__ bias, float* __restrict__ C,
    int M, int N, int K)
{
    __shared__ float As[BKT][BM];
    __shared__ float Bs[BKT][BN];

    const int tid = threadIdx.x;
    const int tx = tid & 15;      // 0..15 -> N direction
    const int ty = tid >> 4;      // 0..15 -> M direction

    const float* Ab = A + (size_t)blockIdx.y * BM * K;
    const float* Wb = W + (size_t)blockIdx.x * BN * K;

    float acc[8][8];
    #pragma unroll
    for (int i = 0; i < 8; i++)
        #pragma unroll
        for (int j = 0; j < 8; j++) acc[i][j] = 0.f;

    for (int k0 = 0; k0 < K; k0 += BKT) {
        // Load 128x16 tiles of A and W (float4 along K, transpose into smem)
        #pragma unroll
        for (int i = 0; i < 2; i++) {
            int f  = tid + i * 256;      // 0..511
            int r  = f >> 2;             // row 0..127
            int kq = (f & 3) << 2;       // k offset 0,4,8,12
            float4 a = *(const float4*)(Ab + (size_t)r * K + k0 + kq);
            As[kq + 0][r] = a.x; As[kq + 1][r] = a.y;
            As[kq + 2][r] = a.z; As[kq + 3][r] = a.w;
            float4 w = *(const float4*)(Wb + (size_t)r * K + k0 + kq);
            Bs[kq + 0][r] = w.x; Bs[kq + 1][r] = w.y;
            Bs[kq + 2][r] = w.z; Bs[kq + 3][r] = w.w;
        }
        __syncthreads();

        #pragma unroll
        for (int kk = 0; kk < BKT; kk++) {
            float4 a0 = *(const float4*)&As[kk][ty * 8];
            float4 a1 = *(const float4*)&As[kk][ty * 8 + 4];
            float4 b0 = *(const float4*)&Bs[kk][tx * 8];
            float4 b1 = *(const float4*)&Bs[kk][tx * 8 + 4];
            float av[8] = {a0.x, a0.y, a0.z, a0.w, a1.x, a1.y, a1.z, a1.w};
            float bv[8] = {b0.x, b0.y, b0.z, b0.w, b1.x, b1.y, b1.z, b1.w};
            #pragma unroll
            for (int i = 0; i < 8; i++)
                #pragma unroll
                for (int j = 0; j < 8; j++)
                    acc[i][j] += av[i] * bv[j];
        }
        __syncthreads();
    }

    const int col0 = blockIdx.x * BN + tx * 8;
    #pragma unroll
    for (int i = 0; i < 8; i++) {
        size_t row = (size_t)blockIdx.y * BM + ty * 8 + i;
        float* crow = C + row * N + col0;
        float4 o0, o1;
        o0.x = acc[i][0] + bias[col0 + 0];
        o0.y = acc[i][1] + bias[col0 + 1];
        o0.z = acc[i][2] + bias[col0 + 2];
        o0.w = acc[i][3] + bias[col0 + 3];
        o1.x = acc[i][4] + bias[col0 + 4];
        o1.y = acc[i][5] + bias[col0 + 5];
        o1.z = acc[i][6] + bias[col0 + 6];
        o1.w = acc[i][7] + bias[col0 + 7];
        *(float4*)(crow)     = o0;
        *(float4*)(crow + 4) = o1;
    }
}

// ---------------------------------------------------------------------------
// Causal flash attention, fp32. One thread owns one query row (q, acc in regs).
// Grid: (T/AQ, B*H), block 128. K/V tiles 64x64 in smem.
// ---------------------------------------------------------------------------
#define AQ 128
#define AK 64

__global__ __launch_bounds__(128) void attn_kernel(
    const float* __restrict__ qkv, float* __restrict__ out)
{
    __shared__ float Ks[AK][HD];
    __shared__ float Vs[AK][HD];

    const int tid = threadIdx.x;
    const int bh  = blockIdx.y;
    const int b   = bh >> 4;
    const int h   = bh & 15;
    const int q0  = blockIdx.x * AQ;
    const int t   = q0 + tid;

    const float* base = qkv + (size_t)b * T_ * C3 + h * HD;

    // q row into registers
    float4 q[16];
    {
        const float* qr = base + (size_t)t * C3;
        #pragma unroll
        for (int i = 0; i < 16; i++) q[i] = *(const float4*)(qr + 4 * i);
    }

    float4 acc[16];
    #pragma unroll
    for (int i = 0; i < 16; i++) acc[i] = make_float4(0.f, 0.f, 0.f, 0.f);
    float m = -INFINITY, l = 0.f;

    for (int j0 = 0; j0 < q0 + AQ; j0 += AK) {
        // Cooperative K/V tile load: 64 rows x 64 floats, 2 threads per row
        {
            int r = tid >> 1;
            int c = (tid & 1) * 32;
            const float* kr = base + (size_t)(j0 + r) * C3 + N_EMBD + c;
            const float* vr = kr + N_EMBD;
            #pragma unroll
            for (int i = 0; i < 8; i++) {
                *(float4*)&Ks[r][c + 4 * i] = *(const float4*)(kr + 4 * i);
                *(float4*)&Vs[r][c + 4 * i] = *(const float4*)(vr + 4 * i);
            }
        }
        __syncthreads();

        const int jmax = min(AK, t - j0 + 1);  // causal: keys j0+j <= t
        for (int j = 0; j < jmax; j++) {
            const float4* kr4 = (const float4*)Ks[j];
            float s0 = 0.f, s1 = 0.f, s2 = 0.f, s3 = 0.f;
            #pragma unroll
            for (int d = 0; d < 16; d += 4) {
                float4 k0 = kr4[d], k1 = kr4[d + 1], k2 = kr4[d + 2], k3 = kr4[d + 3];
                s0 += q[d].x   * k0.x + q[d].y   * k0.y + q[d].z   * k0.z + q[d].w   * k0.w;
                s1 += q[d+1].x * k1.x + q[d+1].y * k1.y + q[d+1].z * k1.z + q[d+1].w * k1.w;
                s2 += q[d+2].x * k2.x + q[d+2].y * k2.y + q[d+2].z * k2.z + q[d+2].w * k2.w;
                s3 += q[d+3].x * k3.x + q[d+3].y * k3.y + q[d+3].z * k3.z + q[d+3].w * k3.w;
            }
            float s = ((s0 + s1) + (s2 + s3)) * 0.125f;  // 1/sqrt(64)

            if (s > m) {  // rare after warmup: rescale running state
                float corr = __expf(m - s);
                m = s;
                l *= corr;
                #pragma unroll
                for (int d = 0; d < 16; d++) {
                    acc[d].x *= corr; acc[d].y *= corr;
                    acc[d].z *= corr; acc[d].w *= corr;
                }
            }
            float p = __expf(s - m);
            l += p;
            const float4* vr4 = (const float4*)Vs[j];
            #pragma unroll
            for (int d = 0; d < 16; d++) {
                float4 v = vr4[d];
                acc[d].x += p * v.x; acc[d].y += p * v.y;
                acc[d].z += p * v.z; acc[d].w += p * v.w;
            }
        }
        __syncthreads();
    }

    const float inv = 1.f / l;
    float* orow = out + (size_t)(b * T_ + t) * N_EMBD + h * HD;
    #pragma unroll
    for (int d = 0; d < 16; d++) {
        float4 o = acc[d];
        o.x *= inv; o.y *= inv; o.z *= inv; o.w *= inv;
        *(float4*)(orow + 4 * d) = o;
    }
}

// ---------------------------------------------------------------------------
extern "C" void kernel_launch(void* const* d_in, const int* in_sizes, int n_in,
                              void* d_out, int out_size)
{
    const float* x      = (const float*)d_in[0];
    const float* qkv_w  = (const float*)d_in[1];
    const float* qkv_b  = (const float*)d_in[2];
    const float* proj_w = (const float*)d_in[3];
    const float* proj_b = (const float*)d_in[4];
    float* out = (float*)d_out;

    float *qkv_s = nullptr, *att_s = nullptr;
    cudaGetSymbolAddress((void**)&qkv_s, g_qkv);
    cudaGetSymbolAddress((void**)&att_s, g_att);

    // 1) QKV GEMM: [8192,1024] @ [3072,1024]^T
    dim3 g1(C3 / BN, M_TOK / BM);
    gemm_abt<<<g1, 256>>>(x, qkv_w, qkv_b, qkv_s, M_TOK, C3, N_EMBD);

    // 2) Causal attention
    dim3 g2(T_ / AQ, B_ * N_HEAD);
    attn_kernel<<<g2, 128>>>(qkv_s, att_s);

    // 3) Output projection: [8192,1024] @ [1024,1024]^T
    dim3 g3(N_EMBD / BN, M_TOK / BM);
    gemm_abt<<<g3, 256>>>(att_s, proj_w, proj_b, out, M_TOK, N_EMBD, N_EMBD);
}

// round 3
// speedup vs baseline: 1.4406x; 1.4406x over previous
#include <cuda_runtime.h>
#include <math.h>
#include <stdint.h>

#define N_HEAD 16
#define N_EMBD 1024
#define HD     64
#define B_     4
#define T_     2048
#define M_TOK  (B_ * T_)
#define C3     (3 * N_EMBD)

// Scratch (device globals — no allocation allowed in kernel_launch)
__device__ float g_qkv[(size_t)M_TOK * C3];     // [B*T, 3C]
__device__ float g_att[(size_t)M_TOK * N_EMBD]; // [B*T, C] attention output

// ---------------------------------------------------------------------------
// TF32 tensor-core GEMM: C[M,N] = A[M,K] @ W[N,K]^T + bias[N]
// Block tile 128x128, BK=16, 256 threads = 8 warps (4 M x 2 N),
// warp tile 32x64 via mma.sync.m16n8k8.tf32 (2 m-tiles x 8 n-tiles).
// Smem padded to 20 floats/row -> conflict-free fragment loads.
// ---------------------------------------------------------------------------
#define PAD 20

__device__ __forceinline__ uint32_t f2tf32(float f) {
    uint32_t r;
    asm("cvt.rna.tf32.f32 %0, %1;" : "=r"(r) : "f"(f));
    return r;
}

__global__ __launch_bounds__(256) void gemm_tf32(
    const float* __restrict__ A, const float* __restrict__ W,
    const float* __restrict__ bias, float* __restrict__ C,
    int M, int N, int K)
{
    __shared__ alignas(16) uint32_t As[128 * PAD];
    __shared__ alignas(16) uint32_t Bs[128 * PAD];

    const int tid   = threadIdx.x;
    const int warp  = tid >> 5;
    const int lane  = tid & 31;
    const int warpM = warp & 3;   // 0..3
    const int warpN = warp >> 2;  // 0..1
    const int g     = lane >> 2;  // 0..7
    const int t     = lane & 3;   // 0..3

    const float* Ab = A + (size_t)blockIdx.y * 128 * K;
    const float* Wb = W + (size_t)blockIdx.x * 128 * K;

    float acc[2][8][4];
    #pragma unroll
    for (int i = 0; i < 2; i++)
        #pragma unroll
        for (int j = 0; j < 8; j++)
            #pragma unroll
            for (int c = 0; c < 4; c++) acc[i][j][c] = 0.f;

    for (int k0 = 0; k0 < K; k0 += 16) {
        // Load 128x16 tiles of A and W, rounding to tf32 at store time.
        #pragma unroll
        for (int i = 0; i < 2; i++) {
            int f  = tid + i * 256;      // 0..511
            int r  = f >> 2;             // row 0..127
            int kq = (f & 3) << 2;       // k offset 0,4,8,12
            float4 a = *(const float4*)(Ab + (size_t)r * K + k0 + kq);
            uint4 at = make_uint4(f2tf32(a.x), f2tf32(a.y), f2tf32(a.z), f2tf32(a.w));
            *(uint4*)&As[r * PAD + kq] = at;
            float4 w = *(const float4*)(Wb + (size_t)r * K + k0 + kq);
            uint4 wt = make_uint4(f2tf32(w.x), f2tf32(w.y), f2tf32(w.z), f2tf32(w.w));
            *(uint4*)&Bs[r * PAD + kq] = wt;
        }
        __syncthreads();

        #pragma unroll
        for (int ks = 0; ks < 16; ks += 8) {
            // A fragments: 2 m-tiles of m16k8
            uint32_t af[2][4];
            #pragma unroll
            for (int tm = 0; tm < 2; tm++) {
                int m = warpM * 32 + tm * 16 + g;
                af[tm][0] = As[m * PAD + ks + t];
                af[tm][1] = As[(m + 8) * PAD + ks + t];
                af[tm][2] = As[m * PAD + ks + t + 4];
                af[tm][3] = As[(m + 8) * PAD + ks + t + 4];
            }
            // B fragments: 8 n-tiles of k8n8
            uint32_t bf[8][2];
            #pragma unroll
            for (int tn = 0; tn < 8; tn++) {
                int n = warpN * 64 + tn * 8 + g;
                bf[tn][0] = Bs[n * PAD + ks + t];
                bf[tn][1] = Bs[n * PAD + ks + t + 4];
            }
            #pragma unroll
            for (int tm = 0; tm < 2; tm++)
                #pragma unroll
                for (int tn = 0; tn < 8; tn++) {
                    asm volatile(
                        "mma.sync.aligned.m16n8k8.row.col.f32.tf32.tf32.f32 "
                        "{%0,%1,%2,%3}, {%4,%5,%6,%7}, {%8,%9}, {%0,%1,%2,%3};"
                        : "+f"(acc[tm][tn][0]), "+f"(acc[tm][tn][1]),
                          "+f"(acc[tm][tn][2]), "+f"(acc[tm][tn][3])
                        : "r"(af[tm][0]), "r"(af[tm][1]), "r"(af[tm][2]), "r"(af[tm][3]),
                          "r"(bf[tn][0]), "r"(bf[tn][1]));
                }
        }
        __syncthreads();
    }

    // Epilogue: c0,c1 -> (row, 2t / 2t+1); c2,c3 -> (row+8, same cols)
    #pragma unroll
    for (int tm = 0; tm < 2; tm++) {
        int row0 = blockIdx.y * 128 + warpM * 32 + tm * 16 + g;
        #pragma unroll
        for (int tn = 0; tn < 8; tn++) {
            int col = blockIdx.x * 128 + warpN * 64 + tn * 8 + 2 * t;
            float bx = __ldg(&bias[col]);
            float by = __ldg(&bias[col + 1]);
            float2 o0 = make_float2(acc[tm][tn][0] + bx, acc[tm][tn][1] + by);
            float2 o1 = make_float2(acc[tm][tn][2] + bx, acc[tm][tn][3] + by);
            *(float2*)(C + (size_t)row0 * N + col)       = o0;
            *(float2*)(C + (size_t)(row0 + 8) * N + col) = o1;
        }
    }
}

// ---------------------------------------------------------------------------
// Causal flash attention, fp32. One thread owns one query row (q, acc in regs).
// Grid: (T/AQ, B*H), block 128. K/V tiles 64x64 in smem.
// ---------------------------------------------------------------------------
#define AQ 128
#define AK 64

__global__ __launch_bounds__(128) void attn_kernel(
    const float* __restrict__ qkv, float* __restrict__ out)
{
    __shared__ float Ks[AK][HD];
    __shared__ float Vs[AK][HD];

    const int tid = threadIdx.x;
    const int bh  = blockIdx.y;
    const int b   = bh >> 4;
    const int h   = bh & 15;
    const int q0  = blockIdx.x * AQ;
    const int t   = q0 + tid;

    const float* base = qkv + (size_t)b * T_ * C3 + h * HD;

    float4 q[16];
    {
        const float* qr = base + (size_t)t * C3;
        #pragma unroll
        for (int i = 0; i < 16; i++) q[i] = *(const float4*)(qr + 4 * i);
    }

    float4 acc[16];
    #pragma unroll
    for (int i = 0; i < 16; i++) acc[i] = make_float4(0.f, 0.f, 0.f, 0.f);
    float m = -INFINITY, l = 0.f;

    for (int j0 = 0; j0 < q0 + AQ; j0 += AK) {
        {
            int r = tid >> 1;
            int c = (tid & 1) * 32;
            const float* kr = base + (size_t)(j0 + r) * C3 + N_EMBD + c;
            const float* vr = kr + N_EMBD;
            #pragma unroll
            for (int i = 0; i < 8; i++) {
                *(float4*)&Ks[r][c + 4 * i] = *(const float4*)(kr + 4 * i);
                *(float4*)&Vs[r][c + 4 * i] = *(const float4*)(vr + 4 * i);
            }
        }
        __syncthreads();

        const int jmax = min(AK, t - j0 + 1);  // causal: keys j0+j <= t
        for (int j = 0; j < jmax; j++) {
            const float4* kr4 = (const float4*)Ks[j];
            float s0 = 0.f, s1 = 0.f, s2 = 0.f, s3 = 0.f;
            #pragma unroll
            for (int d = 0; d < 16; d += 4) {
                float4 k0 = kr4[d], k1 = kr4[d + 1], k2 = kr4[d + 2], k3 = kr4[d + 3];
                s0 += q[d].x   * k0.x + q[d].y   * k0.y + q[d].z   * k0.z + q[d].w   * k0.w;
                s1 += q[d+1].x * k1.x + q[d+1].y * k1.y + q[d+1].z * k1.z + q[d+1].w * k1.w;
                s2 += q[d+2].x * k2.x + q[d+2].y * k2.y + q[d+2].z * k2.z + q[d+2].w * k2.w;
                s3 += q[d+3].x * k3.x + q[d+3].y * k3.y + q[d+3].z * k3.z + q[d+3].w * k3.w;
            }
            float s = ((s0 + s1) + (s2 + s3)) * 0.125f;  // 1/sqrt(64)

            if (s > m) {
                float corr = __expf(m - s);
                m = s;
                l *= corr;
                #pragma unroll
                for (int d = 0; d < 16; d++) {
                    acc[d].x *= corr; acc[d].y *= corr;
                    acc[d].z *= corr; acc[d].w *= corr;
                }
            }
            float p = __expf(s - m);
            l += p;
            const float4* vr4 = (const float4*)Vs[j];
            #pragma unroll
            for (int d = 0; d < 16; d++) {
                float4 v = vr4[d];
                acc[d].x += p * v.x; acc[d].y += p * v.y;
                acc[d].z += p * v.z; acc[d].w += p * v.w;
            }
        }
        __syncthreads();
    }

    const float inv = 1.f / l;
    float* orow = out + (size_t)(b * T_ + t) * N_EMBD + h * HD;
    #pragma unroll
    for (int d = 0; d < 16; d++) {
        float4 o = acc[d];
        o.x *= inv; o.y *= inv; o.z *= inv; o.w *= inv;
        *(float4*)(orow + 4 * d) = o;
    }
}

// ---------------------------------------------------------------------------
extern "C" void kernel_launch(void* const* d_in, const int* in_sizes, int n_in,
                              void* d_out, int out_size)
{
    const float* x      = (const float*)d_in[0];
    const float* qkv_w  = (const float*)d_in[1];
    const float* qkv_b  = (const float*)d_in[2];
    const float* proj_w = (const float*)d_in[3];
    const float* proj_b = (const float*)d_in[4];
    float* out = (float*)d_out;

    float *qkv_s = nullptr, *att_s = nullptr;
    cudaGetSymbolAddress((void**)&qkv_s, g_qkv);
    cudaGetSymbolAddress((void**)&att_s, g_att);

    // 1) QKV GEMM: [8192,1024] @ [3072,1024]^T
    dim3 g1(C3 / 128, M_TOK / 128);
    gemm_tf32<<<g1, 256>>>(x, qkv_w, qkv_b, qkv_s, M_TOK, C3, N_EMBD);

    // 2) Causal attention
    dim3 g2(T_ / AQ, B_ * N_HEAD);
    attn_kernel<<<g2, 128>>>(qkv_s, att_s);

    // 3) Output projection: [8192,1024] @ [1024,1024]^T
    dim3 g3(N_EMBD / 128, M_TOK / 128);
    gemm_tf32<<<g3, 256>>>(att_s, proj_w, proj_b, out, M_TOK, N_EMBD, N_EMBD);
}

// round 5
// speedup vs baseline: 3.0539x; 2.1199x over previous
#include <cuda_runtime.h>
#include <cuda_fp16.h>
#include <math.h>
#include <stdint.h>

#define N_HEAD 16
#define N_EMBD 1024
#define HD     64
#define B_     4
#define T_     2048
#define M_TOK  (B_ * T_)
#define C3     (3 * N_EMBD)

// Scratch (device globals — no allocation allowed in kernel_launch)
__device__ float g_qkv[(size_t)M_TOK * C3];     // [B*T, 3C]
__device__ float g_att[(size_t)M_TOK * N_EMBD]; // [B*T, C] attention output

__device__ __forceinline__ uint32_t f2tf32(float f) {
    uint32_t r;
    asm("cvt.rna.tf32.f32 %0, %1;" : "=r"(r) : "f"(f));
    return r;
}
__device__ __forceinline__ float ex2(float x) {
    float r;
    asm("ex2.approx.ftz.f32 %0, %1;" : "=f"(r) : "f"(x));
    return r;
}

// ---------------------------------------------------------------------------
// TF32 tensor-core GEMM: C[M,N] = A[M,K] @ W[N,K]^T + bias[N]   (unchanged)
// ---------------------------------------------------------------------------
#define PAD 20

__global__ __launch_bounds__(256) void gemm_tf32(
    const float* __restrict__ A, const float* __restrict__ W,
    const float* __restrict__ bias, float* __restrict__ C,
    int M, int N, int K)
{
    __shared__ alignas(16) uint32_t As[128 * PAD];
    __shared__ alignas(16) uint32_t Bs[128 * PAD];

    const int tid   = threadIdx.x;
    const int warp  = tid >> 5;
    const int lane  = tid & 31;
    const int warpM = warp & 3;
    const int warpN = warp >> 2;
    const int g     = lane >> 2;
    const int t     = lane & 3;

    const float* Ab = A + (size_t)blockIdx.y * 128 * K;
    const float* Wb = W + (size_t)blockIdx.x * 128 * K;

    float acc[2][8][4];
    #pragma unroll
    for (int i = 0; i < 2; i++)
        #pragma unroll
        for (int j = 0; j < 8; j++)
            #pragma unroll
            for (int c = 0; c < 4; c++) acc[i][j][c] = 0.f;

    for (int k0 = 0; k0 < K; k0 += 16) {
        #pragma unroll
        for (int i = 0; i < 2; i++) {
            int f  = tid + i * 256;
            int r  = f >> 2;
            int kq = (f & 3) << 2;
            float4 a = *(const float4*)(Ab + (size_t)r * K + k0 + kq);
            uint4 at = make_uint4(f2tf32(a.x), f2tf32(a.y), f2tf32(a.z), f2tf32(a.w));
            *(uint4*)&As[r * PAD + kq] = at;
            float4 w = *(const float4*)(Wb + (size_t)r * K + k0 + kq);
            uint4 wt = make_uint4(f2tf32(w.x), f2tf32(w.y), f2tf32(w.z), f2tf32(w.w));
            *(uint4*)&Bs[r * PAD + kq] = wt;
        }
        __syncthreads();

        #pragma unroll
        for (int ks = 0; ks < 16; ks += 8) {
            uint32_t af[2][4];
            #pragma unroll
            for (int tm = 0; tm < 2; tm++) {
                int m = warpM * 32 + tm * 16 + g;
                af[tm][0] = As[m * PAD + ks + t];
                af[tm][1] = As[(m + 8) * PAD + ks + t];
                af[tm][2] = As[m * PAD + ks + t + 4];
                af[tm][3] = As[(m + 8) * PAD + ks + t + 4];
            }
            uint32_t bf[8][2];
            #pragma unroll
            for (int tn = 0; tn < 8; tn++) {
                int n = warpN * 64 + tn * 8 + g;
                bf[tn][0] = Bs[n * PAD + ks + t];
                bf[tn][1] = Bs[n * PAD + ks + t + 4];
            }
            #pragma unroll
            for (int tm = 0; tm < 2; tm++)
                #pragma unroll
                for (int tn = 0; tn < 8; tn++) {
                    asm volatile(
                        "mma.sync.aligned.m16n8k8.row.col.f32.tf32.tf32.f32 "
                        "{%0,%1,%2,%3}, {%4,%5,%6,%7}, {%8,%9}, {%0,%1,%2,%3};"
                        : "+f"(acc[tm][tn][0]), "+f"(acc[tm][tn][1]),
                          "+f"(acc[tm][tn][2]), "+f"(acc[tm][tn][3])
                        : "r"(af[tm][0]), "r"(af[tm][1]), "r"(af[tm][2]), "r"(af[tm][3]),
                          "r"(bf[tn][0]), "r"(bf[tn][1]));
                }
        }
        __syncthreads();
    }

    #pragma unroll
    for (int tm = 0; tm < 2; tm++) {
        int row0 = blockIdx.y * 128 + warpM * 32 + tm * 16 + g;
        #pragma unroll
        for (int tn = 0; tn < 8; tn++) {
            int col = blockIdx.x * 128 + warpN * 64 + tn * 8 + 2 * t;
            float bx = __ldg(&bias[col]);
            float by = __ldg(&bias[col + 1]);
            float2 o0 = make_float2(acc[tm][tn][0] + bx, acc[tm][tn][1] + by);
            float2 o1 = make_float2(acc[tm][tn][2] + bx, acc[tm][tn][3] + by);
            *(float2*)(C + (size_t)row0 * N + col)       = o0;
            *(float2*)(C + (size_t)(row0 + 8) * N + col) = o1;
        }
    }
}

// ---------------------------------------------------------------------------
// MMA flash attention (FA2 style).
// CTA = one (b,h), 64 query rows. 4 warps x 16 rows.
// QK^T: tf32 m16n8k8 (K in smem). PV: f16 m16n8k16 (P regs -> A frags, V^T smem).
// Q pre-scaled by 0.125*log2(e) so p = ex2(s - m).
// ---------------------------------------------------------------------------
#define KSS 68   // K/Q smem row stride (floats)
#define VTS 72   // V^T smem row stride (halves)

__global__ __launch_bounds__(128) void attn_mma(
    const float* __restrict__ qkv, float* __restrict__ out)
{
    __shared__ alignas(16) uint32_t Ks[64 * KSS];  // K tile tf32 (Q staging first)
    __shared__ alignas(16) __half   Vt[64 * VTS];  // V^T fp16: [d][key]

    const int tid  = threadIdx.x;
    const int warp = tid >> 5;
    const int lane = tid & 31;
    const int g    = lane >> 2;
    const int t    = lane & 3;
    const int b    = blockIdx.y >> 4;
    const int h    = blockIdx.y & 15;
    const int q0   = blockIdx.x * 64;

    const float* base = qkv + (size_t)b * T_ * C3 + h * HD;
    const float qscale = 0.125f * 1.4426950408889634f;  // 1/sqrt(hd) * log2(e)

    // ---- Stage Q tile (scaled tf32) into Ks, pull A-fragments ----
    {
        int r = tid >> 1, c = (tid & 1) * 32;
        const float* qr = base + (size_t)(q0 + r) * C3 + c;
        #pragma unroll
        for (int i = 0; i < 8; i++) {
            float4 v = *(const float4*)(qr + 4 * i);
            Ks[r * KSS + c + 4 * i + 0] = f2tf32(v.x * qscale);
            Ks[r * KSS + c + 4 * i + 1] = f2tf32(v.y * qscale);
            Ks[r * KSS + c + 4 * i + 2] = f2tf32(v.z * qscale);
            Ks[r * KSS + c + 4 * i + 3] = f2tf32(v.w * qscale);
        }
    }
    __syncthreads();

    uint32_t qf[8][4];
    {
        int r0 = warp * 16 + g;
        #pragma unroll
        for (int ks = 0; ks < 8; ks++) {
            qf[ks][0] = Ks[r0 * KSS + ks * 8 + t];
            qf[ks][1] = Ks[(r0 + 8) * KSS + ks * 8 + t];
            qf[ks][2] = Ks[r0 * KSS + ks * 8 + t + 4];
            qf[ks][3] = Ks[(r0 + 8) * KSS + ks * 8 + t + 4];
        }
    }
    __syncthreads();

    float o[8][4];
    #pragma unroll
    for (int tn = 0; tn < 8; tn++)
        #pragma unroll
        for (int c = 0; c < 4; c++) o[tn][c] = 0.f;
    float m0 = -1e30f, m1 = -1e30f, l0 = 0.f, l1 = 0.f;

    for (int j0 = 0; j0 <= q0; j0 += 64) {
        // ---- Load K (tf32) and V (fp16 transposed) tiles ----
        {
            int r = tid >> 1, c = (tid & 1) * 32;
            const float* kr = base + (size_t)(j0 + r) * C3 + N_EMBD + c;
            #pragma unroll
            for (int i = 0; i < 8; i++) {
                float4 v = *(const float4*)(kr + 4 * i);
                Ks[r * KSS + c + 4 * i + 0] = f2tf32(v.x);
                Ks[r * KSS + c + 4 * i + 1] = f2tf32(v.y);
                Ks[r * KSS + c + 4 * i + 2] = f2tf32(v.z);
                Ks[r * KSS + c + 4 * i + 3] = f2tf32(v.w);
            }
            int key = tid & 63, d0 = (tid >> 6) * 32;
            const float* vr = base + (size_t)(j0 + key) * C3 + 2 * N_EMBD + d0;
            #pragma unroll
            for (int i = 0; i < 8; i++) {
                float4 v = *(const float4*)(vr + 4 * i);
                Vt[(d0 + 4 * i + 0) * VTS + key] = __float2half(v.x);
                Vt[(d0 + 4 * i + 1) * VTS + key] = __float2half(v.y);
                Vt[(d0 + 4 * i + 2) * VTS + key] = __float2half(v.z);
                Vt[(d0 + 4 * i + 3) * VTS + key] = __float2half(v.w);
            }
        }
        __syncthreads();

        // ---- S = Q K^T ----
        float acc[8][4];
        #pragma unroll
        for (int tn = 0; tn < 8; tn++)
            #pragma unroll
            for (int c = 0; c < 4; c++) acc[tn][c] = 0.f;

        #pragma unroll
        for (int ks = 0; ks < 8; ks++) {
            #pragma unroll
            for (int tn = 0; tn < 8; tn++) {
                uint32_t b0 = Ks[(tn * 8 + g) * KSS + ks * 8 + t];
                uint32_t b1 = Ks[(tn * 8 + g) * KSS + ks * 8 + t + 4];
                asm volatile(
                    "mma.sync.aligned.m16n8k8.row.col.f32.tf32.tf32.f32 "
                    "{%0,%1,%2,%3}, {%4,%5,%6,%7}, {%8,%9}, {%0,%1,%2,%3};"
                    : "+f"(acc[tn][0]), "+f"(acc[tn][1]),
                      "+f"(acc[tn][2]), "+f"(acc[tn][3])
                    : "r"(qf[ks][0]), "r"(qf[ks][1]), "r"(qf[ks][2]), "r"(qf[ks][3]),
                      "r"(b0), "r"(b1));
            }
        }

        // ---- Causal mask (diagonal tile only) ----
        if (j0 == q0) {
            int r0 = warp * 16 + g;       // query row rel tile
            #pragma unroll
            for (int tn = 0; tn < 8; tn++) {
                int c0 = tn * 8 + 2 * t;  // key col rel tile
                if (c0     > r0)     acc[tn][0] = -1e30f;
                if (c0 + 1 > r0)     acc[tn][1] = -1e30f;
                if (c0     > r0 + 8) acc[tn][2] = -1e30f;
                if (c0 + 1 > r0 + 8) acc[tn][3] = -1e30f;
            }
        }

        // ---- Online softmax ----
        float mx0 = -1e30f, mx1 = -1e30f;
        #pragma unroll
        for (int tn = 0; tn < 8; tn++) {
            mx0 = fmaxf(mx0, fmaxf(acc[tn][0], acc[tn][1]));
            mx1 = fmaxf(mx1, fmaxf(acc[tn][2], acc[tn][3]));
        }
        mx0 = fmaxf(mx0, __shfl_xor_sync(0xffffffffu, mx0, 1));
        mx0 = fmaxf(mx0, __shfl_xor_sync(0xffffffffu, mx0, 2));
        mx1 = fmaxf(mx1, __shfl_xor_sync(0xffffffffu, mx1, 1));
        mx1 = fmaxf(mx1, __shfl_xor_sync(0xffffffffu, mx1, 2));

        float mn0 = fmaxf(m0, mx0), mn1 = fmaxf(m1, mx1);
        float cr0 = ex2(m0 - mn0),  cr1 = ex2(m1 - mn1);
        l0 *= cr0; l1 *= cr1;
        m0 = mn0;  m1 = mn1;
        #pragma unroll
        for (int tn = 0; tn < 8; tn++) {
            o[tn][0] *= cr0; o[tn][1] *= cr0;
            o[tn][2] *= cr1; o[tn][3] *= cr1;
        }

        uint32_t ph01[8], ph23[8];
        #pragma unroll
        for (int tn = 0; tn < 8; tn++) {
            float p0 = ex2(acc[tn][0] - m0);
            float p1 = ex2(acc[tn][1] - m0);
            float p2 = ex2(acc[tn][2] - m1);
            float p3 = ex2(acc[tn][3] - m1);
            l0 += p0 + p1;
            l1 += p2 + p3;
            __half2 h01 = __floats2half2_rn(p0, p1);
            __half2 h23 = __floats2half2_rn(p2, p3);
            ph01[tn] = *(uint32_t*)&h01;
            ph23[tn] = *(uint32_t*)&h23;
        }

        // ---- O += P V ----
        #pragma unroll
        for (int kc = 0; kc < 4; kc++) {
            uint32_t a0 = ph01[2 * kc], a1 = ph23[2 * kc];
            uint32_t a2 = ph01[2 * kc + 1], a3 = ph23[2 * kc + 1];
            #pragma unroll
            for (int tn = 0; tn < 8; tn++) {
                uint32_t b0 = *(const uint32_t*)&Vt[(tn * 8 + g) * VTS + kc * 16 + 2 * t];
                uint32_t b1 = *(const uint32_t*)&Vt[(tn * 8 + g) * VTS + kc * 16 + 2 * t + 8];
                asm volatile(
                    "mma.sync.aligned.m16n8k16.row.col.f32.f16.f16.f32 "
                    "{%0,%1,%2,%3}, {%4,%5,%6,%7}, {%8,%9}, {%0,%1,%2,%3};"
                    : "+f"(o[tn][0]), "+f"(o[tn][1]),
                      "+f"(o[tn][2]), "+f"(o[tn][3])
                    : "r"(a0), "r"(a1), "r"(a2), "r"(a3),
                      "r"(b0), "r"(b1));
            }
        }
        __syncthreads();
    }

    // ---- Finalize: reduce l over quad, normalize, write ----
    l0 += __shfl_xor_sync(0xffffffffu, l0, 1);
    l0 += __shfl_xor_sync(0xffffffffu, l0, 2);
    l1 += __shfl_xor_sync(0xffffffffu, l1, 1);
    l1 += __shfl_xor_sync(0xffffffffu, l1, 2);
    float inv0 = 1.f / l0, inv1 = 1.f / l1;

    int qr = q0 + warp * 16 + g;
    float* orow0 = out + (size_t)(b * T_ + qr) * N_EMBD + h * HD;
    float* orow1 = orow0 + (size_t)8 * N_EMBD;
    #pragma unroll
    for (int tn = 0; tn < 8; tn++) {
        int col = tn * 8 + 2 * t;
        *(float2*)(orow0 + col) = make_float2(o[tn][0] * inv0, o[tn][1] * inv0);
        *(float2*)(orow1 + col) = make_float2(o[tn][2] * inv1, o[tn][3] * inv1);
    }
}

// ---------------------------------------------------------------------------
extern "C" void kernel_launch(void* const* d_in, const int* in_sizes, int n_in,
                              void* d_out, int out_size)
{
    const float* x      = (const float*)d_in[0];
    const float* qkv_w  = (const float*)d_in[1];
    const float* qkv_b  = (const float*)d_in[2];
    const float* proj_w = (const float*)d_in[3];
    const float* proj_b = (const float*)d_in[4];
    float* out = (float*)d_out;

    float *qkv_s = nullptr, *att_s = nullptr;
    cudaGetSymbolAddress((void**)&qkv_s, g_qkv);
    cudaGetSymbolAddress((void**)&att_s, g_att);

    // 1) QKV GEMM: [8192,1024] @ [3072,1024]^T
    dim3 g1(C3 / 128, M_TOK / 128);
    gemm_tf32<<<g1, 256>>>(x, qkv_w, qkv_b, qkv_s, M_TOK, C3, N_EMBD);

    // 2) Causal attention (tensor-core flash)
    dim3 g2(T_ / 64, B_ * N_HEAD);
    attn_mma<<<g2, 128>>>(qkv_s, att_s);

    // 3) Output projection: [8192,1024] @ [1024,1024]^T
    dim3 g3(N_EMBD / 128, M_TOK / 128);
    gemm_tf32<<<g3, 256>>>(att_s, proj_w, proj_b, out, M_TOK, N_EMBD, N_EMBD);
}

// round 6
// speedup vs baseline: 4.3451x; 1.4228x over previous
#include <cuda_runtime.h>
#include <cuda_fp16.h>
#include <math.h>
#include <stdint.h>

#define N_HEAD 16
#define N_EMBD 1024
#define HD     64
#define B_     4
#define T_     2048
#define M_TOK  (B_ * T_)
#define C3     (3 * N_EMBD)

// Scratch (device globals — no allocation allowed in kernel_launch)
__device__ float  g_qkv[(size_t)M_TOK * C3];      // [B*T, 3C] fp32
__device__ __half g_att_h[(size_t)M_TOK * N_EMBD]; // attention out, fp16
__device__ __half g_x_h[(size_t)M_TOK * N_EMBD];   // x in fp16
__device__ __half g_qkvw_h[(size_t)C3 * N_EMBD];   // qkv_w fp16
__device__ __half g_projw_h[(size_t)N_EMBD * N_EMBD]; // proj_w fp16

__device__ __forceinline__ uint32_t f2tf32(float f) {
    uint32_t r;
    asm("cvt.rna.tf32.f32 %0, %1;" : "=r"(r) : "f"(f));
    return r;
}
__device__ __forceinline__ float ex2(float x) {
    float r;
    asm("ex2.approx.ftz.f32 %0, %1;" : "=f"(r) : "f"(x));
    return r;
}
__device__ __forceinline__ uint32_t smem_u32(const void* p) {
    return (uint32_t)__cvta_generic_to_shared(p);
}

// ---------------------------------------------------------------------------
// fp32 -> fp16 convert (vectorized)
// ---------------------------------------------------------------------------
__global__ __launch_bounds__(256) void f2h_kernel(
    const float* __restrict__ in, __half* __restrict__ out, int n4)
{
    int i = blockIdx.x * 256 + threadIdx.x;
    if (i < n4) {
        float4 v = *(const float4*)(in + (size_t)i * 4);
        __half2 lo = __floats2half2_rn(v.x, v.y);
        __half2 hi = __floats2half2_rn(v.z, v.w);
        uint2 o = make_uint2(*(uint32_t*)&lo, *(uint32_t*)&hi);
        *(uint2*)(out + (size_t)i * 4) = o;
    }
}

// ---------------------------------------------------------------------------
// fp16 tensor-core GEMM: C[M,N] = A[M,K] @ W[N,K]^T + bias[N]  (fp32 out)
// 128x128 block tile, BK=32 halves, 2-stage cp.async double buffer.
// 8 warps (4M x 2N), warp tile 32x64, m16n8k16 f16 MMA, ldmatrix A-frags.
// Smem row stride 40 halves (80B): conflict-free ldmatrix + half2 B loads.
// ---------------------------------------------------------------------------
#define HS 40

__global__ __launch_bounds__(256) void gemm_f16(
    const __half* __restrict__ A, const __half* __restrict__ W,
    const float* __restrict__ bias, float* __restrict__ C,
    int M, int N, int K)
{
    __shared__ alignas(16) __half As[2][128 * HS];
    __shared__ alignas(16) __half Bs[2][128 * HS];

    const int tid   = threadIdx.x;
    const int warp  = tid >> 5;
    const int lane  = tid & 31;
    const int warpM = warp & 3;
    const int warpN = warp >> 2;
    const int g     = lane >> 2;
    const int t     = lane & 3;

    const __half* Ab = A + (size_t)blockIdx.y * 128 * K;
    const __half* Wb = W + (size_t)blockIdx.x * 128 * K;

    const int r0 = tid >> 2;          // rows for cp.async (2 per thread)
    const int c0 = (tid & 3) * 8;     // half-offset of 16B chunk

    // Prologue: load stage 0
    {
        #pragma unroll
        for (int i = 0; i < 2; i++) {
            int r = r0 + i * 64;
            uint32_t sa = smem_u32(&As[0][r * HS + c0]);
            asm volatile("cp.async.cg.shared.global [%0], [%1], 16;"
                         :: "r"(sa), "l"(Ab + (size_t)r * K + c0));
            uint32_t sb = smem_u32(&Bs[0][r * HS + c0]);
            asm volatile("cp.async.cg.shared.global [%0], [%1], 16;"
                         :: "r"(sb), "l"(Wb + (size_t)r * K + c0));
        }
        asm volatile("cp.async.commit_group;");
    }

    float acc[2][8][4];
    #pragma unroll
    for (int i = 0; i < 2; i++)
        #pragma unroll
        for (int j = 0; j < 8; j++)
            #pragma unroll
            for (int c = 0; c < 4; c++) acc[i][j][c] = 0.f;

    const int KT = K >> 5;  // BK=32
    for (int kt = 0; kt < KT; kt++) {
        const int s = kt & 1;
        asm volatile("cp.async.wait_group 0;" ::: "memory");
        __syncthreads();

        if (kt + 1 < KT) {
            const int ns = s ^ 1;
            const int k0 = (kt + 1) << 5;
            #pragma unroll
            for (int i = 0; i < 2; i++) {
                int r = r0 + i * 64;
                uint32_t sa = smem_u32(&As[ns][r * HS + c0]);
                asm volatile("cp.async.cg.shared.global [%0], [%1], 16;"
                             :: "r"(sa), "l"(Ab + (size_t)r * K + k0 + c0));
                uint32_t sb = smem_u32(&Bs[ns][r * HS + c0]);
                asm volatile("cp.async.cg.shared.global [%0], [%1], 16;"
                             :: "r"(sb), "l"(Wb + (size_t)r * K + k0 + c0));
            }
            asm volatile("cp.async.commit_group;");
        }

        #pragma unroll
        for (int ks = 0; ks < 2; ks++) {
            uint32_t af[2][4];
            #pragma unroll
            for (int tm = 0; tm < 2; tm++) {
                int row = warpM * 32 + tm * 16 + (lane & 15);
                uint32_t addr = smem_u32(&As[s][row * HS + ks * 16 + (lane >> 4) * 8]);
                asm volatile("ldmatrix.sync.aligned.m8n8.x4.shared.b16 "
                             "{%0,%1,%2,%3}, [%4];"
                             : "=r"(af[tm][0]), "=r"(af[tm][1]),
                               "=r"(af[tm][2]), "=r"(af[tm][3])
                             : "r"(addr));
            }
            #pragma unroll
            for (int tn = 0; tn < 8; tn++) {
                int n = warpN * 64 + tn * 8 + g;
                uint32_t b0 = *(const uint32_t*)&Bs[s][n * HS + ks * 16 + t * 2];
                uint32_t b1 = *(const uint32_t*)&Bs[s][n * HS + ks * 16 + t * 2 + 8];
                #pragma unroll
                for (int tm = 0; tm < 2; tm++) {
                    asm volatile(
                        "mma.sync.aligned.m16n8k16.row.col.f32.f16.f16.f32 "
                        "{%0,%1,%2,%3}, {%4,%5,%6,%7}, {%8,%9}, {%0,%1,%2,%3};"
                        : "+f"(acc[tm][tn][0]), "+f"(acc[tm][tn][1]),
                          "+f"(acc[tm][tn][2]), "+f"(acc[tm][tn][3])
                        : "r"(af[tm][0]), "r"(af[tm][1]),
                          "r"(af[tm][2]), "r"(af[tm][3]),
                          "r"(b0), "r"(b1));
                }
            }
        }
        __syncthreads();
    }

    #pragma unroll
    for (int tm = 0; tm < 2; tm++) {
        int row = blockIdx.y * 128 + warpM * 32 + tm * 16 + g;
        #pragma unroll
        for (int tn = 0; tn < 8; tn++) {
            int col = blockIdx.x * 128 + warpN * 64 + tn * 8 + 2 * t;
            float bx = __ldg(&bias[col]);
            float by = __ldg(&bias[col + 1]);
            float2 o0 = make_float2(acc[tm][tn][0] + bx, acc[tm][tn][1] + by);
            float2 o1 = make_float2(acc[tm][tn][2] + bx, acc[tm][tn][3] + by);
            *(float2*)(C + (size_t)row * N + col)       = o0;
            *(float2*)(C + (size_t)(row + 8) * N + col) = o1;
        }
    }
}

// ---------------------------------------------------------------------------
// MMA flash attention (unchanged from R3 except fp16 output).
// ---------------------------------------------------------------------------
#define KSS 68
#define VTS 72

__global__ __launch_bounds__(128) void attn_mma(
    const float* __restrict__ qkv, __half* __restrict__ out)
{
    __shared__ alignas(16) uint32_t Ks[64 * KSS];
    __shared__ alignas(16) __half   Vt[64 * VTS];

    const int tid  = threadIdx.x;
    const int warp = tid >> 5;
    const int lane = tid & 31;
    const int g    = lane >> 2;
    const int t    = lane & 3;
    const int b    = blockIdx.y >> 4;
    const int h    = blockIdx.y & 15;
    const int q0   = blockIdx.x * 64;

    const float* base = qkv + (size_t)b * T_ * C3 + h * HD;
    const float qscale = 0.125f * 1.4426950408889634f;

    {
        int r = tid >> 1, c = (tid & 1) * 32;
        const float* qr = base + (size_t)(q0 + r) * C3 + c;
        #pragma unroll
        for (int i = 0; i < 8; i++) {
            float4 v = *(const float4*)(qr + 4 * i);
            Ks[r * KSS + c + 4 * i + 0] = f2tf32(v.x * qscale);
            Ks[r * KSS + c + 4 * i + 1] = f2tf32(v.y * qscale);
            Ks[r * KSS + c + 4 * i + 2] = f2tf32(v.z * qscale);
            Ks[r * KSS + c + 4 * i + 3] = f2tf32(v.w * qscale);
        }
    }
    __syncthreads();

    uint32_t qf[8][4];
    {
        int r0 = warp * 16 + g;
        #pragma unroll
        for (int ks = 0; ks < 8; ks++) {
            qf[ks][0] = Ks[r0 * KSS + ks * 8 + t];
            qf[ks][1] = Ks[(r0 + 8) * KSS + ks * 8 + t];
            qf[ks][2] = Ks[r0 * KSS + ks * 8 + t + 4];
            qf[ks][3] = Ks[(r0 + 8) * KSS + ks * 8 + t + 4];
        }
    }
    __syncthreads();

    float o[8][4];
    #pragma unroll
    for (int tn = 0; tn < 8; tn++)
        #pragma unroll
        for (int c = 0; c < 4; c++) o[tn][c] = 0.f;
    float m0 = -1e30f, m1 = -1e30f, l0 = 0.f, l1 = 0.f;

    for (int j0 = 0; j0 <= q0; j0 += 64) {
        {
            int r = tid >> 1, c = (tid & 1) * 32;
            const float* kr = base + (size_t)(j0 + r) * C3 + N_EMBD + c;
            #pragma unroll
            for (int i = 0; i < 8; i++) {
                float4 v = *(const float4*)(kr + 4 * i);
                Ks[r * KSS + c + 4 * i + 0] = f2tf32(v.x);
                Ks[r * KSS + c + 4 * i + 1] = f2tf32(v.y);
                Ks[r * KSS + c + 4 * i + 2] = f2tf32(v.z);
                Ks[r * KSS + c + 4 * i + 3] = f2tf32(v.w);
            }
            int key = tid & 63, d0 = (tid >> 6) * 32;
            const float* vr = base + (size_t)(j0 + key) * C3 + 2 * N_EMBD + d0;
            #pragma unroll
            for (int i = 0; i < 8; i++) {
                float4 v = *(const float4*)(vr + 4 * i);
                Vt[(d0 + 4 * i + 0) * VTS + key] = __float2half(v.x);
                Vt[(d0 + 4 * i + 1) * VTS + key] = __float2half(v.y);
                Vt[(d0 + 4 * i + 2) * VTS + key] = __float2half(v.z);
                Vt[(d0 + 4 * i + 3) * VTS + key] = __float2half(v.w);
            }
        }
        __syncthreads();

        float acc[8][4];
        #pragma unroll
        for (int tn = 0; tn < 8; tn++)
            #pragma unroll
            for (int c = 0; c < 4; c++) acc[tn][c] = 0.f;

        #pragma unroll
        for (int ks = 0; ks < 8; ks++) {
            #pragma unroll
            for (int tn = 0; tn < 8; tn++) {
                uint32_t b0 = Ks[(tn * 8 + g) * KSS + ks * 8 + t];
                uint32_t b1 = Ks[(tn * 8 + g) * KSS + ks * 8 + t + 4];
                asm volatile(
                    "mma.sync.aligned.m16n8k8.row.col.f32.tf32.tf32.f32 "
                    "{%0,%1,%2,%3}, {%4,%5,%6,%7}, {%8,%9}, {%0,%1,%2,%3};"
                    : "+f"(acc[tn][0]), "+f"(acc[tn][1]),
                      "+f"(acc[tn][2]), "+f"(acc[tn][3])
                    : "r"(qf[ks][0]), "r"(qf[ks][1]), "r"(qf[ks][2]), "r"(qf[ks][3]),
                      "r"(b0), "r"(b1));
            }
        }

        if (j0 == q0) {
            int r0 = warp * 16 + g;
            #pragma unroll
            for (int tn = 0; tn < 8; tn++) {
                int c0 = tn * 8 + 2 * t;
                if (c0     > r0)     acc[tn][0] = -1e30f;
                if (c0 + 1 > r0)     acc[tn][1] = -1e30f;
                if (c0     > r0 + 8) acc[tn][2] = -1e30f;
                if (c0 + 1 > r0 + 8) acc[tn][3] = -1e30f;
            }
        }

        float mx0 = -1e30f, mx1 = -1e30f;
        #pragma unroll
        for (int tn = 0; tn < 8; tn++) {
            mx0 = fmaxf(mx0, fmaxf(acc[tn][0], acc[tn][1]));
            mx1 = fmaxf(mx1, fmaxf(acc[tn][2], acc[tn][3]));
        }
        mx0 = fmaxf(mx0, __shfl_xor_sync(0xffffffffu, mx0, 1));
        mx0 = fmaxf(mx0, __shfl_xor_sync(0xffffffffu, mx0, 2));
        mx1 = fmaxf(mx1, __shfl_xor_sync(0xffffffffu, mx1, 1));
        mx1 = fmaxf(mx1, __shfl_xor_sync(0xffffffffu, mx1, 2));

        float mn0 = fmaxf(m0, mx0), mn1 = fmaxf(m1, mx1);
        float cr0 = ex2(m0 - mn0),  cr1 = ex2(m1 - mn1);
        l0 *= cr0; l1 *= cr1;
        m0 = mn0;  m1 = mn1;
        #pragma unroll
        for (int tn = 0; tn < 8; tn++) {
            o[tn][0] *= cr0; o[tn][1] *= cr0;
            o[tn][2] *= cr1; o[tn][3] *= cr1;
        }

        uint32_t ph01[8], ph23[8];
        #pragma unroll
        for (int tn = 0; tn < 8; tn++) {
            float p0 = ex2(acc[tn][0] - m0);
            float p1 = ex2(acc[tn][1] - m0);
            float p2 = ex2(acc[tn][2] - m1);
            float p3 = ex2(acc[tn][3] - m1);
            l0 += p0 + p1;
            l1 += p2 + p3;
            __half2 h01 = __floats2half2_rn(p0, p1);
            __half2 h23 = __floats2half2_rn(p2, p3);
            ph01[tn] = *(uint32_t*)&h01;
            ph23[tn] = *(uint32_t*)&h23;
        }

        #pragma unroll
        for (int kc = 0; kc < 4; kc++) {
            uint32_t a0 = ph01[2 * kc], a1 = ph23[2 * kc];
            uint32_t a2 = ph01[2 * kc + 1], a3 = ph23[2 * kc + 1];
            #pragma unroll
            for (int tn = 0; tn < 8; tn++) {
                uint32_t b0 = *(const uint32_t*)&Vt[(tn * 8 + g) * VTS + kc * 16 + 2 * t];
                uint32_t b1 = *(const uint32_t*)&Vt[(tn * 8 + g) * VTS + kc * 16 + 2 * t + 8];
                asm volatile(
                    "mma.sync.aligned.m16n8k16.row.col.f32.f16.f16.f32 "
                    "{%0,%1,%2,%3}, {%4,%5,%6,%7}, {%8,%9}, {%0,%1,%2,%3};"
                    : "+f"(o[tn][0]), "+f"(o[tn][1]),
                      "+f"(o[tn][2]), "+f"(o[tn][3])
                    : "r"(a0), "r"(a1), "r"(a2), "r"(a3),
                      "r"(b0), "r"(b1));
            }
        }
        __syncthreads();
    }

    l0 += __shfl_xor_sync(0xffffffffu, l0, 1);
    l0 += __shfl_xor_sync(0xffffffffu, l0, 2);
    l1 += __shfl_xor_sync(0xffffffffu, l1, 1);
    l1 += __shfl_xor_sync(0xffffffffu, l1, 2);
    float inv0 = 1.f / l0, inv1 = 1.f / l1;

    int qr = q0 + warp * 16 + g;
    __half* orow0 = out + (size_t)(b * T_ + qr) * N_EMBD + h * HD;
    __half* orow1 = orow0 + (size_t)8 * N_EMBD;
    #pragma unroll
    for (int tn = 0; tn < 8; tn++) {
        int col = tn * 8 + 2 * t;
        __half2 w0 = __floats2half2_rn(o[tn][0] * inv0, o[tn][1] * inv0);
        __half2 w1 = __floats2half2_rn(o[tn][2] * inv1, o[tn][3] * inv1);
        *(uint32_t*)(orow0 + col) = *(uint32_t*)&w0;
        *(uint32_t*)(orow1 + col) = *(uint32_t*)&w1;
    }
}

// ---------------------------------------------------------------------------
extern "C" void kernel_launch(void* const* d_in, const int* in_sizes, int n_in,
                              void* d_out, int out_size)
{
    const float* x      = (const float*)d_in[0];
    const float* qkv_w  = (const float*)d_in[1];
    const float* qkv_b  = (const float*)d_in[2];
    const float* proj_w = (const float*)d_in[3];
    const float* proj_b = (const float*)d_in[4];
    float* out = (float*)d_out;

    float  *qkv_s = nullptr;
    __half *att_h = nullptr, *x_h = nullptr, *qkvw_h = nullptr, *projw_h = nullptr;
    cudaGetSymbolAddress((void**)&qkv_s,   g_qkv);
    cudaGetSymbolAddress((void**)&att_h,   g_att_h);
    cudaGetSymbolAddress((void**)&x_h,     g_x_h);
    cudaGetSymbolAddress((void**)&qkvw_h,  g_qkvw_h);
    cudaGetSymbolAddress((void**)&projw_h, g_projw_h);

    // 0) fp32 -> fp16 converts
    {
        int n4x = (M_TOK * N_EMBD) / 4;
        f2h_kernel<<<(n4x + 255) / 256, 256>>>(x, x_h, n4x);
        int n4q = (C3 * N_EMBD) / 4;
        f2h_kernel<<<(n4q + 255) / 256, 256>>>(qkv_w, qkvw_h, n4q);
        int n4p = (N_EMBD * N_EMBD) / 4;
        f2h_kernel<<<(n4p + 255) / 256, 256>>>(proj_w, projw_h, n4p);
    }

    // 1) QKV GEMM (fp16 in, fp32 out): [8192,1024] @ [3072,1024]^T
    dim3 g1(C3 / 128, M_TOK / 128);
    gemm_f16<<<g1, 256>>>(x_h, qkvw_h, qkv_b, qkv_s, M_TOK, C3, N_EMBD);

    // 2) Causal attention (tensor-core flash), fp16 out
    dim3 g2(T_ / 64, B_ * N_HEAD);
    attn_mma<<<g2, 128>>>(qkv_s, att_h);

    // 3) Output projection: [8192,1024] @ [1024,1024]^T
    dim3 g3(N_EMBD / 128, M_TOK / 128);
    gemm_f16<<<g3, 256>>>(att_h, projw_h, proj_b, out, M_TOK, N_EMBD, N_EMBD);
}

// round 8
// speedup vs baseline: 7.9685x; 1.8339x over previous
#include <cuda_runtime.h>
#include <cuda_fp16.h>
#include <math.h>
#include <stdint.h>

#define N_HEAD 16
#define N_EMBD 1024
#define HD     64
#define B_     4
#define T_     2048
#define M_TOK  (B_ * T_)
#define C3     (3 * N_EMBD)

// Scratch (device globals — no allocation allowed in kernel_launch)
__device__ __half g_qkv_h[(size_t)M_TOK * C3];        // [B*T, 3C] fp16
__device__ __half g_att_h[(size_t)M_TOK * N_EMBD];    // attention out, fp16
__device__ __half g_x_h[(size_t)M_TOK * N_EMBD];      // x in fp16
__device__ __half g_qkvw_h[(size_t)C3 * N_EMBD];      // qkv_w fp16
__device__ __half g_projw_h[(size_t)N_EMBD * N_EMBD]; // proj_w fp16

__device__ __forceinline__ float ex2(float x) {
    float r;
    asm("ex2.approx.ftz.f32 %0, %1;" : "=f"(r) : "f"(x));
    return r;
}
__device__ __forceinline__ uint32_t smem_u32(const void* p) {
    return (uint32_t)__cvta_generic_to_shared(p);
}

// ---------------------------------------------------------------------------
// fp32 -> fp16 convert (vectorized)
// ---------------------------------------------------------------------------
__global__ __launch_bounds__(256) void f2h_kernel(
    const float* __restrict__ in, __half* __restrict__ out, int n4)
{
    int i = blockIdx.x * 256 + threadIdx.x;
    if (i < n4) {
        float4 v = *(const float4*)(in + (size_t)i * 4);
        __half2 lo = __floats2half2_rn(v.x, v.y);
        __half2 hi = __floats2half2_rn(v.z, v.w);
        uint2 o = make_uint2(*(uint32_t*)&lo, *(uint32_t*)&hi);
        *(uint2*)(out + (size_t)i * 4) = o;
    }
}

// ---------------------------------------------------------------------------
// fp16 tensor-core GEMM: C[M,N] = A[M,K] @ W[N,K]^T + bias[N]
// Output type templated (fp32 final / fp16 intermediate). Unchanged from R5.
// ---------------------------------------------------------------------------
#define HS 40

template <typename OT>
__global__ __launch_bounds__(256) void gemm_f16(
    const __half* __restrict__ A, const __half* __restrict__ W,
    const float* __restrict__ bias, OT* __restrict__ C,
    int M, int N, int K)
{
    __shared__ alignas(16) __half As[2][128 * HS];
    __shared__ alignas(16) __half Bs[2][128 * HS];

    const int tid   = threadIdx.x;
    const int warp  = tid >> 5;
    const int lane  = tid & 31;
    const int warpM = warp & 3;
    const int warpN = warp >> 2;
    const int g     = lane >> 2;
    const int t     = lane & 3;

    const __half* Ab = A + (size_t)blockIdx.y * 128 * K;
    const __half* Wb = W + (size_t)blockIdx.x * 128 * K;

    const int r0 = tid >> 2;
    const int c0 = (tid & 3) * 8;

    {
        #pragma unroll
        for (int i = 0; i < 2; i++) {
            int r = r0 + i * 64;
            uint32_t sa = smem_u32(&As[0][r * HS + c0]);
            asm volatile("cp.async.cg.shared.global [%0], [%1], 16;"
                         :: "r"(sa), "l"(Ab + (size_t)r * K + c0));
            uint32_t sb = smem_u32(&Bs[0][r * HS + c0]);
            asm volatile("cp.async.cg.shared.global [%0], [%1], 16;"
                         :: "r"(sb), "l"(Wb + (size_t)r * K + c0));
        }
        asm volatile("cp.async.commit_group;");
    }

    float acc[2][8][4];
    #pragma unroll
    for (int i = 0; i < 2; i++)
        #pragma unroll
        for (int j = 0; j < 8; j++)
            #pragma unroll
            for (int c = 0; c < 4; c++) acc[i][j][c] = 0.f;

    const int KT = K >> 5;
    for (int kt = 0; kt < KT; kt++) {
        const int s = kt & 1;
        asm volatile("cp.async.wait_group 0;" ::: "memory");
        __syncthreads();

        if (kt + 1 < KT) {
            const int ns = s ^ 1;
            const int k0 = (kt + 1) << 5;
            #pragma unroll
            for (int i = 0; i < 2; i++) {
                int r = r0 + i * 64;
                uint32_t sa = smem_u32(&As[ns][r * HS + c0]);
                asm volatile("cp.async.cg.shared.global [%0], [%1], 16;"
                             :: "r"(sa), "l"(Ab + (size_t)r * K + k0 + c0));
                uint32_t sb = smem_u32(&Bs[ns][r * HS + c0]);
                asm volatile("cp.async.cg.shared.global [%0], [%1], 16;"
                             :: "r"(sb), "l"(Wb + (size_t)r * K + k0 + c0));
            }
            asm volatile("cp.async.commit_group;");
        }

        #pragma unroll
        for (int ks = 0; ks < 2; ks++) {
            uint32_t af[2][4];
            #pragma unroll
            for (int tm = 0; tm < 2; tm++) {
                int row = warpM * 32 + tm * 16 + (lane & 15);
                uint32_t addr = smem_u32(&As[s][row * HS + ks * 16 + (lane >> 4) * 8]);
                asm volatile("ldmatrix.sync.aligned.m8n8.x4.shared.b16 "
                             "{%0,%1,%2,%3}, [%4];"
                             : "=r"(af[tm][0]), "=r"(af[tm][1]),
                               "=r"(af[tm][2]), "=r"(af[tm][3])
                             : "r"(addr));
            }
            #pragma unroll
            for (int tn = 0; tn < 8; tn++) {
                int n = warpN * 64 + tn * 8 + g;
                uint32_t b0 = *(const uint32_t*)&Bs[s][n * HS + ks * 16 + t * 2];
                uint32_t b1 = *(const uint32_t*)&Bs[s][n * HS + ks * 16 + t * 2 + 8];
                #pragma unroll
                for (int tm = 0; tm < 2; tm++) {
                    asm volatile(
                        "mma.sync.aligned.m16n8k16.row.col.f32.f16.f16.f32 "
                        "{%0,%1,%2,%3}, {%4,%5,%6,%7}, {%8,%9}, {%0,%1,%2,%3};"
                        : "+f"(acc[tm][tn][0]), "+f"(acc[tm][tn][1]),
                          "+f"(acc[tm][tn][2]), "+f"(acc[tm][tn][3])
                        : "r"(af[tm][0]), "r"(af[tm][1]),
                          "r"(af[tm][2]), "r"(af[tm][3]),
                          "r"(b0), "r"(b1));
                }
            }
        }
        __syncthreads();
    }

    #pragma unroll
    for (int tm = 0; tm < 2; tm++) {
        int row = blockIdx.y * 128 + warpM * 32 + tm * 16 + g;
        #pragma unroll
        for (int tn = 0; tn < 8; tn++) {
            int col = blockIdx.x * 128 + warpN * 64 + tn * 8 + 2 * t;
            float bx = __ldg(&bias[col]);
            float by = __ldg(&bias[col + 1]);
            float v00 = acc[tm][tn][0] + bx, v01 = acc[tm][tn][1] + by;
            float v10 = acc[tm][tn][2] + bx, v11 = acc[tm][tn][3] + by;
            if constexpr (sizeof(OT) == 2) {
                __half2 h0 = __floats2half2_rn(v00, v01);
                __half2 h1 = __floats2half2_rn(v10, v11);
                *(uint32_t*)((__half*)C + (size_t)row * N + col)       = *(uint32_t*)&h0;
                *(uint32_t*)((__half*)C + (size_t)(row + 8) * N + col) = *(uint32_t*)&h1;
            } else {
                *(float2*)((float*)C + (size_t)row * N + col)       = make_float2(v00, v01);
                *(float2*)((float*)C + (size_t)(row + 8) * N + col) = make_float2(v10, v11);
            }
        }
    }
}

// ---------------------------------------------------------------------------
// fp16 MMA flash attention, FA2 style.
// CTA = one (b,h) x 128 queries, 8 warps x 16 rows, 64-key tiles,
// cp.async double-buffered K/V. Q staged through the K buffers (smem reuse),
// fragments held in registers for the whole kernel.
// Row stride QS=72 halves (64 data + 8 pad): conflict-free ldmatrix +
// half2 B loads (bank = (4g+t) mod 32, bijective).
// ---------------------------------------------------------------------------
#define QS 72

__global__ __launch_bounds__(256) void attn_f16(
    const __half* __restrict__ qkv, __half* __restrict__ out)
{
    __shared__ alignas(16) __half Ks[2][64 * QS];  // also Q staging (flat 128 rows)
    __shared__ alignas(16) __half Vs[2][64 * QS];

    const int tid  = threadIdx.x;
    const int warp = tid >> 5;
    const int lane = tid & 31;
    const int g    = lane >> 2;
    const int t    = lane & 3;
    const int b    = blockIdx.y >> 4;
    const int h    = blockIdx.y & 15;
    const int q0   = blockIdx.x * 128;

    const __half* base = qkv + (size_t)b * T_ * C3 + h * HD;
    const float qscale = 0.125f * 1.4426950408889634f;  // 1/sqrt(64) * log2(e)

    __half* Kflat = &Ks[0][0];  // Ks[2] is contiguous: 128 rows of QS

    // ---- Stage Q tile (128 x 64) through Kflat, extract fragments ----
    {
        #pragma unroll
        for (int i = 0; i < 4; i++) {
            int c = tid + i * 256;          // 0..1023 chunks of 8 halves
            int r = c >> 3, co = (c & 7) * 8;
            uint32_t sq = smem_u32(&Kflat[r * QS + co]);
            asm volatile("cp.async.cg.shared.global [%0], [%1], 16;"
                         :: "r"(sq), "l"(base + (size_t)(q0 + r) * C3 + co));
        }
        asm volatile("cp.async.commit_group;");
        asm volatile("cp.async.wait_group 0;" ::: "memory");
    }
    __syncthreads();

    uint32_t qf[4][4];
    {
        int row = warp * 16 + (lane & 15);
        #pragma unroll
        for (int ks = 0; ks < 4; ks++) {
            uint32_t addr = smem_u32(&Kflat[row * QS + ks * 16 + (lane >> 4) * 8]);
            asm volatile("ldmatrix.sync.aligned.m8n8.x4.shared.b16 "
                         "{%0,%1,%2,%3}, [%4];"
                         : "=r"(qf[ks][0]), "=r"(qf[ks][1]),
                           "=r"(qf[ks][2]), "=r"(qf[ks][3])
                         : "r"(addr));
        }
    }
    __syncthreads();   // Q fragments safe in regs; Ks may be overwritten now

    // ---- Prologue: K/V tile 0 ----
    {
        #pragma unroll
        for (int i = 0; i < 2; i++) {
            int c = tid + i * 256;          // 0..511
            int r = c >> 3, co = (c & 7) * 8;
            uint32_t sk = smem_u32(&Ks[0][r * QS + co]);
            asm volatile("cp.async.cg.shared.global [%0], [%1], 16;"
                         :: "r"(sk), "l"(base + (size_t)r * C3 + N_EMBD + co));
            uint32_t sv = smem_u32(&Vs[0][r * QS + co]);
            asm volatile("cp.async.cg.shared.global [%0], [%1], 16;"
                         :: "r"(sv), "l"(base + (size_t)r * C3 + 2 * N_EMBD + co));
        }
        asm volatile("cp.async.commit_group;");
        asm volatile("cp.async.wait_group 0;" ::: "memory");
    }
    __syncthreads();

    float o[8][4];
    #pragma unroll
    for (int tn = 0; tn < 8; tn++)
        #pragma unroll
        for (int c = 0; c < 4; c++) o[tn][c] = 0.f;
    float m0 = -1e30f, m1 = -1e30f, l0 = 0.f, l1 = 0.f;

    const int NT = (q0 >> 6) + 2;
    for (int jt = 0; jt < NT; jt++) {
        const int s  = jt & 1;
        const int j0 = jt << 6;

        // Issue next tile's K/V into the other buffer
        if (jt + 1 < NT) {
            const int ns = s ^ 1;
            const int nj = j0 + 64;
            #pragma unroll
            for (int i = 0; i < 2; i++) {
                int c = tid + i * 256;
                int r = c >> 3, co = (c & 7) * 8;
                uint32_t sk = smem_u32(&Ks[ns][r * QS + co]);
                asm volatile("cp.async.cg.shared.global [%0], [%1], 16;"
                             :: "r"(sk), "l"(base + (size_t)(nj + r) * C3 + N_EMBD + co));
                uint32_t sv = smem_u32(&Vs[ns][r * QS + co]);
                asm volatile("cp.async.cg.shared.global [%0], [%1], 16;"
                             :: "r"(sv), "l"(base + (size_t)(nj + r) * C3 + 2 * N_EMBD + co));
            }
            asm volatile("cp.async.commit_group;");
        }

        const bool active = (j0 <= q0 + warp * 16 + 15);
        if (active) {
            // ---- S = Q K^T (f16, fp32 acc) ----
            float acc[8][4];
            #pragma unroll
            for (int tn = 0; tn < 8; tn++)
                #pragma unroll
                for (int c = 0; c < 4; c++) acc[tn][c] = 0.f;

            #pragma unroll
            for (int ks = 0; ks < 4; ks++) {
                #pragma unroll
                for (int tn = 0; tn < 8; tn++) {
                    uint32_t b0 = *(const uint32_t*)&Ks[s][(tn * 8 + g) * QS + ks * 16 + 2 * t];
                    uint32_t b1 = *(const uint32_t*)&Ks[s][(tn * 8 + g) * QS + ks * 16 + 2 * t + 8];
                    asm volatile(
                        "mma.sync.aligned.m16n8k16.row.col.f32.f16.f16.f32 "
                        "{%0,%1,%2,%3}, {%4,%5,%6,%7}, {%8,%9}, {%0,%1,%2,%3};"
                        : "+f"(acc[tn][0]), "+f"(acc[tn][1]),
                          "+f"(acc[tn][2]), "+f"(acc[tn][3])
                        : "r"(qf[ks][0]), "r"(qf[ks][1]), "r"(qf[ks][2]), "r"(qf[ks][3]),
                          "r"(b0), "r"(b1));
                }
            }

            // ---- scale + causal mask ----
            #pragma unroll
            for (int tn = 0; tn < 8; tn++) {
                acc[tn][0] *= qscale; acc[tn][1] *= qscale;
                acc[tn][2] *= qscale; acc[tn][3] *= qscale;
            }
            if (j0 + 63 > q0 + warp * 16) {
                int r0 = q0 + warp * 16 + g;
                #pragma unroll
                for (int tn = 0; tn < 8; tn++) {
                    int c0 = j0 + tn * 8 + 2 * t;
                    if (c0     > r0)     acc[tn][0] = -1e30f;
                    if (c0 + 1 > r0)     acc[tn][1] = -1e30f;
                    if (c0     > r0 + 8) acc[tn][2] = -1e30f;
                    if (c0 + 1 > r0 + 8) acc[tn][3] = -1e30f;
                }
            }

            // ---- online softmax ----
            float mx0 = -1e30f, mx1 = -1e30f;
            #pragma unroll
            for (int tn = 0; tn < 8; tn++) {
                mx0 = fmaxf(mx0, fmaxf(acc[tn][0], acc[tn][1]));
                mx1 = fmaxf(mx1, fmaxf(acc[tn][2], acc[tn][3]));
            }
            mx0 = fmaxf(mx0, __shfl_xor_sync(0xffffffffu, mx0, 1));
            mx0 = fmaxf(mx0, __shfl_xor_sync(0xffffffffu, mx0, 2));
            mx1 = fmaxf(mx1, __shfl_xor_sync(0xffffffffu, mx1, 1));
            mx1 = fmaxf(mx1, __shfl_xor_sync(0xffffffffu, mx1, 2));

            float mn0 = fmaxf(m0, mx0), mn1 = fmaxf(m1, mx1);
            float cr0 = ex2(m0 - mn0),  cr1 = ex2(m1 - mn1);
            l0 *= cr0; l1 *= cr1;
            m0 = mn0;  m1 = mn1;
            #pragma unroll
            for (int tn = 0; tn < 8; tn++) {
                o[tn][0] *= cr0; o[tn][1] *= cr0;
                o[tn][2] *= cr1; o[tn][3] *= cr1;
            }

            uint32_t ph01[8], ph23[8];
            #pragma unroll
            for (int tn = 0; tn < 8; tn++) {
                float p0 = ex2(acc[tn][0] - m0);
                float p1 = ex2(acc[tn][1] - m0);
                float p2 = ex2(acc[tn][2] - m1);
                float p3 = ex2(acc[tn][3] - m1);
                l0 += p0 + p1;
                l1 += p2 + p3;
                __half2 h01 = __floats2half2_rn(p0, p1);
                __half2 h23 = __floats2half2_rn(p2, p3);
                ph01[tn] = *(uint32_t*)&h01;
                ph23[tn] = *(uint32_t*)&h23;
            }

            // ---- O += P V (V frags via ldmatrix.x4.trans) ----
            #pragma unroll
            for (int kc = 0; kc < 4; kc++) {
                uint32_t a0 = ph01[2 * kc],     a1 = ph23[2 * kc];
                uint32_t a2 = ph01[2 * kc + 1], a3 = ph23[2 * kc + 1];
                #pragma unroll
                for (int tp = 0; tp < 4; tp++) {
                    uint32_t v0, v1, v2, v3;
                    uint32_t addr = smem_u32(
                        &Vs[s][(kc * 16 + ((lane >> 3) & 1) * 8 + (lane & 7)) * QS
                               + (tp * 2 + (lane >> 4)) * 8]);
                    asm volatile("ldmatrix.sync.aligned.m8n8.x4.trans.shared.b16 "
                                 "{%0,%1,%2,%3}, [%4];"
                                 : "=r"(v0), "=r"(v1), "=r"(v2), "=r"(v3)
                                 : "r"(addr));
                    asm volatile(
                        "mma.sync.aligned.m16n8k16.row.col.f32.f16.f16.f32 "
                        "{%0,%1,%2,%3}, {%4,%5,%6,%7}, {%8,%9}, {%0,%1,%2,%3};"
                        : "+f"(o[tp * 2][0]), "+f"(o[tp * 2][1]),
                          "+f"(o[tp * 2][2]), "+f"(o[tp * 2][3])
                        : "r"(a0), "r"(a1), "r"(a2), "r"(a3), "r"(v0), "r"(v1));
                    asm volatile(
                        "mma.sync.aligned.m16n8k16.row.col.f32.f16.f16.f32 "
                        "{%0,%1,%2,%3}, {%4,%5,%6,%7}, {%8,%9}, {%0,%1,%2,%3};"
                        : "+f"(o[tp * 2 + 1][0]), "+f"(o[tp * 2 + 1][1]),
                          "+f"(o[tp * 2 + 1][2]), "+f"(o[tp * 2 + 1][3])
                        : "r"(a0), "r"(a1), "r"(a2), "r"(a3), "r"(v2), "r"(v3));
                }
            }
        }

        if (jt + 1 < NT)
            asm volatile("cp.async.wait_group 0;" ::: "memory");
        __syncthreads();
    }

    // ---- Finalize ----
    l0 += __shfl_xor_sync(0xffffffffu, l0, 1);
    l0 += __shfl_xor_sync(0xffffffffu, l0, 2);
    l1 += __shfl_xor_sync(0xffffffffu, l1, 1);
    l1 += __shfl_xor_sync(0xffffffffu, l1, 2);
    float inv0 = 1.f / l0, inv1 = 1.f / l1;

    int qr = q0 + warp * 16 + g;
    __half* orow0 = out + (size_t)(b * T_ + qr) * N_EMBD + h * HD;
    __half* orow1 = orow0 + (size_t)8 * N_EMBD;
    #pragma unroll
    for (int tn = 0; tn < 8; tn++) {
        int col = tn * 8 + 2 * t;
        __half2 w0 = __floats2half2_rn(o[tn][0] * inv0, o[tn][1] * inv0);
        __half2 w1 = __floats2half2_rn(o[tn][2] * inv1, o[tn][3] * inv1);
        *(uint32_t*)(orow0 + col) = *(uint32_t*)&w0;
        *(uint32_t*)(orow1 + col) = *(uint32_t*)&w1;
    }
}

// ---------------------------------------------------------------------------
extern "C" void kernel_launch(void* const* d_in, const int* in_sizes, int n_in,
                              void* d_out, int out_size)
{
    const float* x      = (const float*)d_in[0];
    const float* qkv_w  = (const float*)d_in[1];
    const float* qkv_b  = (const float*)d_in[2];
    const float* proj_w = (const float*)d_in[3];
    const float* proj_b = (const float*)d_in[4];
    float* out = (float*)d_out;

    __half *qkv_h = nullptr, *att_h = nullptr, *x_h = nullptr,
           *qkvw_h = nullptr, *projw_h = nullptr;
    cudaGetSymbolAddress((void**)&qkv_h,   g_qkv_h);
    cudaGetSymbolAddress((void**)&att_h,   g_att_h);
    cudaGetSymbolAddress((void**)&x_h,     g_x_h);
    cudaGetSymbolAddress((void**)&qkvw_h,  g_qkvw_h);
    cudaGetSymbolAddress((void**)&projw_h, g_projw_h);

    // 0) fp32 -> fp16 converts
    {
        int n4x = (M_TOK * N_EMBD) / 4;
        f2h_kernel<<<(n4x + 255) / 256, 256>>>(x, x_h, n4x);
        int n4q = (C3 * N_EMBD) / 4;
        f2h_kernel<<<(n4q + 255) / 256, 256>>>(qkv_w, qkvw_h, n4q);
        int n4p = (N_EMBD * N_EMBD) / 4;
        f2h_kernel<<<(n4p + 255) / 256, 256>>>(proj_w, projw_h, n4p);
    }

    // 1) QKV GEMM (fp16 in, fp16 out): [8192,1024] @ [3072,1024]^T
    dim3 g1(C3 / 128, M_TOK / 128);
    gemm_f16<__half><<<g1, 256>>>(x_h, qkvw_h, qkv_b, qkv_h, M_TOK, C3, N_EMBD);

    // 2) Causal attention (fp16 flash), fp16 out
    dim3 g2(T_ / 128, B_ * N_HEAD);
    attn_f16<<<g2, 256>>>(qkv_h, att_h);

    // 3) Output projection (fp32 out): [8192,1024] @ [1024,1024]^T
    dim3 g3(N_EMBD / 128, M_TOK / 128);
    gemm_f16<float><<<g3, 256>>>(att_h, projw_h, proj_b, out, M_TOK, N_EMBD, N_EMBD);
}

// round 10
// speedup vs baseline: 9.0422x; 1.1347x over previous
#include <cuda_runtime.h>
#include <cuda_fp16.h>
#include <math.h>
#include <stdint.h>

#define N_HEAD 16
#define N_EMBD 1024
#define HD     64
#define B_     4
#define T_     2048
#define M_TOK  (B_ * T_)
#define C3     (3 * N_EMBD)

// Scratch (device globals — no allocation allowed in kernel_launch)
__device__ __half g_qkv_h[(size_t)M_TOK * C3];        // [B*T, 3C] fp16
__device__ __half g_att_h[(size_t)M_TOK * N_EMBD];    // attention out, fp16
__device__ __half g_x_h[(size_t)M_TOK * N_EMBD];      // x in fp16
__device__ __half g_qkvw_h[(size_t)C3 * N_EMBD];      // qkv_w fp16
__device__ __half g_projw_h[(size_t)N_EMBD * N_EMBD]; // proj_w fp16

__device__ __forceinline__ float ex2(float x) {
    float r;
    asm("ex2.approx.ftz.f32 %0, %1;" : "=f"(r) : "f"(x));
    return r;
}
__device__ __forceinline__ uint32_t smem_u32(const void* p) {
    return (uint32_t)__cvta_generic_to_shared(p);
}

// ---------------------------------------------------------------------------
// fp32 -> fp16 convert (vectorized)
// ---------------------------------------------------------------------------
__global__ __launch_bounds__(256) void f2h_kernel(
    const float* __restrict__ in, __half* __restrict__ out, int n4)
{
    int i = blockIdx.x * 256 + threadIdx.x;
    if (i < n4) {
        float4 v = *(const float4*)(in + (size_t)i * 4);
        __half2 lo = __floats2half2_rn(v.x, v.y);
        __half2 hi = __floats2half2_rn(v.z, v.w);
        uint2 o = make_uint2(*(uint32_t*)&lo, *(uint32_t*)&hi);
        *(uint2*)(out + (size_t)i * 4) = o;
    }
}

// ---------------------------------------------------------------------------
// fp16 tensor-core GEMM v2: C[M,N] = A[M,K] @ W[N,K]^T + bias[N]
// 128x128 block tile, BK=32, 3-stage cp.async pipeline (wait_group 1),
// XOR-swizzled smem (stride 32 halves, chunk c ^ ((r^(r>>2))&3)),
// ldmatrix.x4 for both A and B fragments. 8 warps (4M x 2N).
// ---------------------------------------------------------------------------
// swizzled half-offset of 16B chunk c in row r (stride 32 halves)
__device__ __forceinline__ int swz(int r, int c) {
    return r * 32 + ((c ^ (r ^ (r >> 2))) & 3) * 8 + (c & ~3) * 8;
}
// (c is 0..3 here, so (c & ~3) == 0; kept simple below by inlining)

template <typename OT>
__global__ __launch_bounds__(256) void gemm_f16(
    const __half* __restrict__ A, const __half* __restrict__ W,
    const float* __restrict__ bias, OT* __restrict__ C,
    int M, int N, int K)
{
    __shared__ alignas(16) __half As[3][128 * 32];
    __shared__ alignas(16) __half Bs[3][128 * 32];

    const int tid   = threadIdx.x;
    const int warp  = tid >> 5;
    const int lane  = tid & 31;
    const int warpM = warp & 3;
    const int warpN = warp >> 2;
    const int g     = lane >> 2;
    const int t     = lane & 3;

    const __half* Ab = A + (size_t)blockIdx.y * 128 * K;
    const __half* Wb = W + (size_t)blockIdx.x * 128 * K;

    const int lr = tid >> 2;       // load row (0..63), +64 on second pass
    const int lc = tid & 3;        // load chunk (16B) within 64B row

    const int KT = K >> 5;         // #32-wide K tiles

    // issue one 128x32 A tile + 128x32 W tile into stage st
    auto issue = [&](int kt, int st) {
        const int k0 = kt << 5;
        #pragma unroll
        for (int i = 0; i < 2; i++) {
            int r  = lr + i * 64;
            int pc = (lc ^ (r ^ (r >> 2))) & 3;
            uint32_t sa = smem_u32(&As[st][r * 32 + pc * 8]);
            asm volatile("cp.async.cg.shared.global [%0], [%1], 16;"
                         :: "r"(sa), "l"(Ab + (size_t)r * K + k0 + lc * 8));
            uint32_t sb = smem_u32(&Bs[st][r * 32 + pc * 8]);
            asm volatile("cp.async.cg.shared.global [%0], [%1], 16;"
                         :: "r"(sb), "l"(Wb + (size_t)r * K + k0 + lc * 8));
        }
        asm volatile("cp.async.commit_group;");
    };

    // Prologue: tiles 0 and 1 in flight
    issue(0, 0);
    issue(1, 1);

    float acc[2][8][4];
    #pragma unroll
    for (int i = 0; i < 2; i++)
        #pragma unroll
        for (int j = 0; j < 8; j++)
            #pragma unroll
            for (int c = 0; c < 4; c++) acc[i][j][c] = 0.f;

    int s = 0;
    for (int kt = 0; kt < KT; kt++) {
        asm volatile("cp.async.wait_group 1;" ::: "memory");
        __syncthreads();

        if (kt + 2 < KT) {
            int ns = s + 2; if (ns >= 3) ns -= 3;
            issue(kt + 2, ns);
        }

        #pragma unroll
        for (int ks = 0; ks < 2; ks++) {
            // A fragments: 2 x ldmatrix.x4 (m16k16 tiles)
            uint32_t af[2][4];
            #pragma unroll
            for (int tm = 0; tm < 2; tm++) {
                int row = warpM * 32 + tm * 16 + (lane & 15);
                int c   = ks * 2 + (lane >> 4);
                int pc  = (c ^ (row ^ (row >> 2))) & 3;
                uint32_t addr = smem_u32(&As[s][row * 32 + pc * 8]);
                asm volatile("ldmatrix.sync.aligned.m8n8.x4.shared.b16 "
                             "{%0,%1,%2,%3}, [%4];"
                             : "=r"(af[tm][0]), "=r"(af[tm][1]),
                               "=r"(af[tm][2]), "=r"(af[tm][3])
                             : "r"(addr));
            }
            // B fragments: 4 x ldmatrix.x4, each covers two n8 tiles
            uint32_t bf[8][2];
            #pragma unroll
            for (int tnp = 0; tnp < 4; tnp++) {
                int n  = warpN * 64 + tnp * 16 + ((lane >> 4) << 3) + (lane & 7);
                int c  = ks * 2 + ((lane >> 3) & 1);
                int pc = (c ^ (n ^ (n >> 2))) & 3;
                uint32_t addr = smem_u32(&Bs[s][n * 32 + pc * 8]);
                asm volatile("ldmatrix.sync.aligned.m8n8.x4.shared.b16 "
                             "{%0,%1,%2,%3}, [%4];"
                             : "=r"(bf[2 * tnp][0]),     "=r"(bf[2 * tnp][1]),
                               "=r"(bf[2 * tnp + 1][0]), "=r"(bf[2 * tnp + 1][1])
                             : "r"(addr));
            }
            #pragma unroll
            for (int tn = 0; tn < 8; tn++)
                #pragma unroll
                for (int tm = 0; tm < 2; tm++) {
                    asm volatile(
                        "mma.sync.aligned.m16n8k16.row.col.f32.f16.f16.f32 "
                        "{%0,%1,%2,%3}, {%4,%5,%6,%7}, {%8,%9}, {%0,%1,%2,%3};"
                        : "+f"(acc[tm][tn][0]), "+f"(acc[tm][tn][1]),
                          "+f"(acc[tm][tn][2]), "+f"(acc[tm][tn][3])
                        : "r"(af[tm][0]), "r"(af[tm][1]),
                          "r"(af[tm][2]), "r"(af[tm][3]),
                          "r"(bf[tn][0]), "r"(bf[tn][1]));
                }
        }
        if (++s == 3) s = 0;
    }

    #pragma unroll
    for (int tm = 0; tm < 2; tm++) {
        int row = blockIdx.y * 128 + warpM * 32 + tm * 16 + g;
        #pragma unroll
        for (int tn = 0; tn < 8; tn++) {
            int col = blockIdx.x * 128 + warpN * 64 + tn * 8 + 2 * t;
            float bx = __ldg(&bias[col]);
            float by = __ldg(&bias[col + 1]);
            float v00 = acc[tm][tn][0] + bx, v01 = acc[tm][tn][1] + by;
            float v10 = acc[tm][tn][2] + bx, v11 = acc[tm][tn][3] + by;
            if constexpr (sizeof(OT) == 2) {
                __half2 h0 = __floats2half2_rn(v00, v01);
                __half2 h1 = __floats2half2_rn(v10, v11);
                *(uint32_t*)((__half*)C + (size_t)row * N + col)       = *(uint32_t*)&h0;
                *(uint32_t*)((__half*)C + (size_t)(row + 8) * N + col) = *(uint32_t*)&h1;
            } else {
                *(float2*)((float*)C + (size_t)row * N + col)       = make_float2(v00, v01);
                *(float2*)((float*)C + (size_t)(row + 8) * N + col) = make_float2(v10, v11);
            }
        }
    }
}

// ---------------------------------------------------------------------------
// fp16 MMA flash attention (unchanged from R7 passing version).
// ---------------------------------------------------------------------------
#define QS 72

__global__ __launch_bounds__(256) void attn_f16(
    const __half* __restrict__ qkv, __half* __restrict__ out)
{
    __shared__ alignas(16) __half Ks[2][64 * QS];  // also Q staging (flat 128 rows)
    __shared__ alignas(16) __half Vs[2][64 * QS];

    const int tid  = threadIdx.x;
    const int warp = tid >> 5;
    const int lane = tid & 31;
    const int g    = lane >> 2;
    const int t    = lane & 3;
    const int b    = blockIdx.y >> 4;
    const int h    = blockIdx.y & 15;
    const int q0   = blockIdx.x * 128;

    const __half* base = qkv + (size_t)b * T_ * C3 + h * HD;
    const float qscale = 0.125f * 1.4426950408889634f;  // 1/sqrt(64) * log2(e)

    __half* Kflat = &Ks[0][0];

    // ---- Stage Q tile (128 x 64) through Kflat, extract fragments ----
    {
        #pragma unroll
        for (int i = 0; i < 4; i++) {
            int c = tid + i * 256;
            int r = c >> 3, co = (c & 7) * 8;
            uint32_t sq = smem_u32(&Kflat[r * QS + co]);
            asm volatile("cp.async.cg.shared.global [%0], [%1], 16;"
                         :: "r"(sq), "l"(base + (size_t)(q0 + r) * C3 + co));
        }
        asm volatile("cp.async.commit_group;");
        asm volatile("cp.async.wait_group 0;" ::: "memory");
    }
    __syncthreads();

    uint32_t qf[4][4];
    {
        int row = warp * 16 + (lane & 15);
        #pragma unroll
        for (int ks = 0; ks < 4; ks++) {
            uint32_t addr = smem_u32(&Kflat[row * QS + ks * 16 + (lane >> 4) * 8]);
            asm volatile("ldmatrix.sync.aligned.m8n8.x4.shared.b16 "
                         "{%0,%1,%2,%3}, [%4];"
                         : "=r"(qf[ks][0]), "=r"(qf[ks][1]),
                           "=r"(qf[ks][2]), "=r"(qf[ks][3])
                         : "r"(addr));
        }
    }
    __syncthreads();

    // ---- Prologue: K/V tile 0 ----
    {
        #pragma unroll
        for (int i = 0; i < 2; i++) {
            int c = tid + i * 256;
            int r = c >> 3, co = (c & 7) * 8;
            uint32_t sk = smem_u32(&Ks[0][r * QS + co]);
            asm volatile("cp.async.cg.shared.global [%0], [%1], 16;"
                         :: "r"(sk), "l"(base + (size_t)r * C3 + N_EMBD + co));
            uint32_t sv = smem_u32(&Vs[0][r * QS + co]);
            asm volatile("cp.async.cg.shared.global [%0], [%1], 16;"
                         :: "r"(sv), "l"(base + (size_t)r * C3 + 2 * N_EMBD + co));
        }
        asm volatile("cp.async.commit_group;");
        asm volatile("cp.async.wait_group 0;" ::: "memory");
    }
    __syncthreads();

    float o[8][4];
    #pragma unroll
    for (int tn = 0; tn < 8; tn++)
        #pragma unroll
        for (int c = 0; c < 4; c++) o[tn][c] = 0.f;
    float m0 = -1e30f, m1 = -1e30f, l0 = 0.f, l1 = 0.f;

    const int NT = (q0 >> 6) + 2;
    for (int jt = 0; jt < NT; jt++) {
        const int s  = jt & 1;
        const int j0 = jt << 6;

        if (jt + 1 < NT) {
            const int ns = s ^ 1;
            const int nj = j0 + 64;
            #pragma unroll
            for (int i = 0; i < 2; i++) {
                int c = tid + i * 256;
                int r = c >> 3, co = (c & 7) * 8;
                uint32_t sk = smem_u32(&Ks[ns][r * QS + co]);
                asm volatile("cp.async.cg.shared.global [%0], [%1], 16;"
                             :: "r"(sk), "l"(base + (size_t)(nj + r) * C3 + N_EMBD + co));
                uint32_t sv = smem_u32(&Vs[ns][r * QS + co]);
                asm volatile("cp.async.cg.shared.global [%0], [%1], 16;"
                             :: "r"(sv), "l"(base + (size_t)(nj + r) * C3 + 2 * N_EMBD + co));
            }
            asm volatile("cp.async.commit_group;");
        }

        const bool active = (j0 <= q0 + warp * 16 + 15);
        if (active) {
            float acc[8][4];
            #pragma unroll
            for (int tn = 0; tn < 8; tn++)
                #pragma unroll
                for (int c = 0; c < 4; c++) acc[tn][c] = 0.f;

            #pragma unroll
            for (int ks = 0; ks < 4; ks++) {
                #pragma unroll
                for (int tn = 0; tn < 8; tn++) {
                    uint32_t b0 = *(const uint32_t*)&Ks[s][(tn * 8 + g) * QS + ks * 16 + 2 * t];
                    uint32_t b1 = *(const uint32_t*)&Ks[s][(tn * 8 + g) * QS + ks * 16 + 2 * t + 8];
                    asm volatile(
                        "mma.sync.aligned.m16n8k16.row.col.f32.f16.f16.f32 "
                        "{%0,%1,%2,%3}, {%4,%5,%6,%7}, {%8,%9}, {%0,%1,%2,%3};"
                        : "+f"(acc[tn][0]), "+f"(acc[tn][1]),
                          "+f"(acc[tn][2]), "+f"(acc[tn][3])
                        : "r"(qf[ks][0]), "r"(qf[ks][1]), "r"(qf[ks][2]), "r"(qf[ks][3]),
                          "r"(b0), "r"(b1));
                }
            }

            #pragma unroll
            for (int tn = 0; tn < 8; tn++) {
                acc[tn][0] *= qscale; acc[tn][1] *= qscale;
                acc[tn][2] *= qscale; acc[tn][3] *= qscale;
            }
            if (j0 + 63 > q0 + warp * 16) {
                int r0 = q0 + warp * 16 + g;
                #pragma unroll
                for (int tn = 0; tn < 8; tn++) {
                    int c0 = j0 + tn * 8 + 2 * t;
                    if (c0     > r0)     acc[tn][0] = -1e30f;
                    if (c0 + 1 > r0)     acc[tn][1] = -1e30f;
                    if (c0     > r0 + 8) acc[tn][2] = -1e30f;
                    if (c0 + 1 > r0 + 8) acc[tn][3] = -1e30f;
                }
            }

            float mx0 = -1e30f, mx1 = -1e30f;
            #pragma unroll
            for (int tn = 0; tn < 8; tn++) {
                mx0 = fmaxf(mx0, fmaxf(acc[tn][0], acc[tn][1]));
                mx1 = fmaxf(mx1, fmaxf(acc[tn][2], acc[tn][3]));
            }
            mx0 = fmaxf(mx0, __shfl_xor_sync(0xffffffffu, mx0, 1));
            mx0 = fmaxf(mx0, __shfl_xor_sync(0xffffffffu, mx0, 2));
            mx1 = fmaxf(mx1, __shfl_xor_sync(0xffffffffu, mx1, 1));
            mx1 = fmaxf(mx1, __shfl_xor_sync(0xffffffffu, mx1, 2));

            float mn0 = fmaxf(m0, mx0), mn1 = fmaxf(m1, mx1);
            float cr0 = ex2(m0 - mn0),  cr1 = ex2(m1 - mn1);
            l0 *= cr0; l1 *= cr1;
            m0 = mn0;  m1 = mn1;
            #pragma unroll
            for (int tn = 0; tn < 8; tn++) {
                o[tn][0] *= cr0; o[tn][1] *= cr0;
                o[tn][2] *= cr1; o[tn][3] *= cr1;
            }

            uint32_t ph01[8], ph23[8];
            #pragma unroll
            for (int tn = 0; tn < 8; tn++) {
                float p0 = ex2(acc[tn][0] - m0);
                float p1 = ex2(acc[tn][1] - m0);
                float p2 = ex2(acc[tn][2] - m1);
                float p3 = ex2(acc[tn][3] - m1);
                l0 += p0 + p1;
                l1 += p2 + p3;
                __half2 h01 = __floats2half2_rn(p0, p1);
                __half2 h23 = __floats2half2_rn(p2, p3);
                ph01[tn] = *(uint32_t*)&h01;
                ph23[tn] = *(uint32_t*)&h23;
            }

            #pragma unroll
            for (int kc = 0; kc < 4; kc++) {
                uint32_t a0 = ph01[2 * kc],     a1 = ph23[2 * kc];
                uint32_t a2 = ph01[2 * kc + 1], a3 = ph23[2 * kc + 1];
                #pragma unroll
                for (int tp = 0; tp < 4; tp++) {
                    uint32_t v0, v1, v2, v3;
                    uint32_t addr = smem_u32(
                        &Vs[s][(kc * 16 + ((lane >> 3) & 1) * 8 + (lane & 7)) * QS
                               + (tp * 2 + (lane >> 4)) * 8]);
                    asm volatile("ldmatrix.sync.aligned.m8n8.x4.trans.shared.b16 "
                                 "{%0,%1,%2,%3}, [%4];"
                                 : "=r"(v0), "=r"(v1), "=r"(v2), "=r"(v3)
                                 : "r"(addr));
                    asm volatile(
                        "mma.sync.aligned.m16n8k16.row.col.f32.f16.f16.f32 "
                        "{%0,%1,%2,%3}, {%4,%5,%6,%7}, {%8,%9}, {%0,%1,%2,%3};"
                        : "+f"(o[tp * 2][0]), "+f"(o[tp * 2][1]),
                          "+f"(o[tp * 2][2]), "+f"(o[tp * 2][3])
                        : "r"(a0), "r"(a1), "r"(a2), "r"(a3), "r"(v0), "r"(v1));
                    asm volatile(
                        "mma.sync.aligned.m16n8k16.row.col.f32.f16.f16.f32 "
                        "{%0,%1,%2,%3}, {%4,%5,%6,%7}, {%8,%9}, {%0,%1,%2,%3};"
                        : "+f"(o[tp * 2 + 1][0]), "+f"(o[tp * 2 + 1][1]),
                          "+f"(o[tp * 2 + 1][2]), "+f"(o[tp * 2 + 1][3])
                        : "r"(a0), "r"(a1), "r"(a2), "r"(a3), "r"(v2), "r"(v3));
                }
            }
        }

        if (jt + 1 < NT)
            asm volatile("cp.async.wait_group 0;" ::: "memory");
        __syncthreads();
    }

    l0 += __shfl_xor_sync(0xffffffffu, l0, 1);
    l0 += __shfl_xor_sync(0xffffffffu, l0, 2);
    l1 += __shfl_xor_sync(0xffffffffu, l1, 1);
    l1 += __shfl_xor_sync(0xffffffffu, l1, 2);
    float inv0 = 1.f / l0, inv1 = 1.f / l1;

    int qr = q0 + warp * 16 + g;
    __half* orow0 = out + (size_t)(b * T_ + qr) * N_EMBD + h * HD;
    __half* orow1 = orow0 + (size_t)8 * N_EMBD;
    #pragma unroll
    for (int tn = 0; tn < 8; tn++) {
        int col = tn * 8 + 2 * t;
        __half2 w0 = __floats2half2_rn(o[tn][0] * inv0, o[tn][1] * inv0);
        __half2 w1 = __floats2half2_rn(o[tn][2] * inv1, o[tn][3] * inv1);
        *(uint32_t*)(orow0 + col) = *(uint32_t*)&w0;
        *(uint32_t*)(orow1 + col) = *(uint32_t*)&w1;
    }
}

// ---------------------------------------------------------------------------
extern "C" void kernel_launch(void* const* d_in, const int* in_sizes, int n_in,
                              void* d_out, int out_size)
{
    const float* x      = (const float*)d_in[0];
    const float* qkv_w  = (const float*)d_in[1];
    const float* qkv_b  = (const float*)d_in[2];
    const float* proj_w = (const float*)d_in[3];
    const float* proj_b = (const float*)d_in[4];
    float* out = (float*)d_out;

    __half *qkv_h = nullptr, *att_h = nullptr, *x_h = nullptr,
           *qkvw_h = nullptr, *projw_h = nullptr;
    cudaGetSymbolAddress((void**)&qkv_h,   g_qkv_h);
    cudaGetSymbolAddress((void**)&att_h,   g_att_h);
    cudaGetSymbolAddress((void**)&x_h,     g_x_h);
    cudaGetSymbolAddress((void**)&qkvw_h,  g_qkvw_h);
    cudaGetSymbolAddress((void**)&projw_h, g_projw_h);

    // 0) fp32 -> fp16 converts
    {
        int n4x = (M_TOK * N_EMBD) / 4;
        f2h_kernel<<<(n4x + 255) / 256, 256>>>(x, x_h, n4x);
        int n4q = (C3 * N_EMBD) / 4;
        f2h_kernel<<<(n4q + 255) / 256, 256>>>(qkv_w, qkvw_h, n4q);
        int n4p = (N_EMBD * N_EMBD) / 4;
        f2h_kernel<<<(n4p + 255) / 256, 256>>>(proj_w, projw_h, n4p);
    }

    // 1) QKV GEMM (fp16 in, fp16 out): [8192,1024] @ [3072,1024]^T
    dim3 g1(C3 / 128, M_TOK / 128);
    gemm_f16<__half><<<g1, 256>>>(x_h, qkvw_h, qkv_b, qkv_h, M_TOK, C3, N_EMBD);

    // 2) Causal attention (fp16 flash), fp16 out
    dim3 g2(T_ / 128, B_ * N_HEAD);
    attn_f16<<<g2, 256>>>(qkv_h, att_h);

    // 3) Output projection (fp32 out): [8192,1024] @ [1024,1024]^T
    dim3 g3(N_EMBD / 128, M_TOK / 128);
    gemm_f16<float><<<g3, 256>>>(att_h, projw_h, proj_b, out, M_TOK, N_EMBD, N_EMBD);
}